// round 2
// baseline (speedup 1.0000x reference)
#include <cuda_runtime.h>
#include <math.h>

// Problem constants (fixed instance)
constexpr int NP   = 1024;   // N == N_ (train/test points)
constexpr int LT   = 4;      // tasks
constexpr int RNK_MAX = 8;
constexpr int NTOT = 1088;   // RHS width: 1024 Cx cols + 1 ytilde col + 63 pad
constexpr int NKB  = 16;     // 1024 / 64 block steps

// Output offsets (fp32 elements)
constexpr size_t OFF_FMEAN = 0;
constexpr size_t OFF_FVAR  = 4096;
constexpr size_t OFF_NOISE = OFF_FVAR + (size_t)4096 * 4096;
constexpr size_t OFF_OUT4  = OFF_NOISE + (size_t)4096 * 4096;

// -------- device scratch (static, no allocation) --------
__device__ float g_A[LT * NP * NP];          // lambda_c*C + I, then Cholesky L (lower)
__device__ float g_B[LT * NP * NTOT];        // RHS -> solution P_c
__device__ float g_H[LT * NP * NTOT];        // H_c = Cx^T * P_c  (col 1024 = g_c)
__device__ float g_Cx[NP * NP];              // rbf(X, test_X)
__device__ float g_Cxx[NP * NP];             // rbf(test_X, test_X)
__device__ float g_Linv[LT * NKB * 64 * 64]; // per-step 64x64 diag-block inverses
__device__ float g_lambda[LT];
__device__ float g_R[LT * LT];               // R = U^T Dn^{-1/2}
__device__ float g_M[LT * LT];               // M = R * T
__device__ float g_Tm[LT * LT];              // task_K
__device__ float g_noise[LT];                // exp(log_noise)

// =====================================================================
// Small setup: task_K, 4x4 Jacobi eigendecomposition, R, M (fp64)
// =====================================================================
__global__ void k_setup(const float* __restrict__ cf,
                        const float* __restrict__ log_var,
                        const float* __restrict__ log_noise,
                        int rank)
{
    if (threadIdx.x != 0) return;
    double T[LT][LT], Tt[LT][LT], U[LT][LT], sv[LT];
    for (int a = 0; a < LT; a++) sv[a] = exp(-0.5 * (double)log_noise[a]);
    for (int a = 0; a < LT; a++)
        for (int b = 0; b < LT; b++) {
            double s = 0.0;
            for (int r = 0; r < rank && r < RNK_MAX; r++)
                s += (double)cf[a * rank + r] * (double)cf[b * rank + r];
            if (a == b) s += exp((double)log_var[a]);
            T[a][b] = s;
        }
    for (int a = 0; a < LT; a++)
        for (int b = 0; b < LT; b++) {
            Tt[a][b] = sv[a] * sv[b] * T[a][b];
            U[a][b] = (a == b) ? 1.0 : 0.0;
        }
    // cyclic Jacobi
    for (int sweep = 0; sweep < 60; sweep++) {
        double off = 0.0;
        for (int p = 0; p < LT; p++)
            for (int q = p + 1; q < LT; q++) off += Tt[p][q] * Tt[p][q];
        if (off < 1e-28) break;
        for (int p = 0; p < LT; p++)
            for (int q = p + 1; q < LT; q++) {
                double apq = Tt[p][q];
                if (fabs(apq) < 1e-300) continue;
                double tau = (Tt[q][q] - Tt[p][p]) / (2.0 * apq);
                double tt = ((tau >= 0.0) ? 1.0 : -1.0) / (fabs(tau) + sqrt(1.0 + tau * tau));
                double cc = 1.0 / sqrt(1.0 + tt * tt);
                double ss = tt * cc;
                for (int k = 0; k < LT; k++) {      // A = A*J
                    double akp = Tt[k][p], akq = Tt[k][q];
                    Tt[k][p] = cc * akp - ss * akq;
                    Tt[k][q] = ss * akp + cc * akq;
                }
                for (int k = 0; k < LT; k++) {      // A = J^T*A
                    double apk = Tt[p][k], aqk = Tt[q][k];
                    Tt[p][k] = cc * apk - ss * aqk;
                    Tt[q][k] = ss * apk + cc * aqk;
                }
                for (int k = 0; k < LT; k++) {      // U = U*J
                    double ukp = U[k][p], ukq = U[k][q];
                    U[k][p] = cc * ukp - ss * ukq;
                    U[k][q] = ss * ukp + cc * ukq;
                }
            }
    }
    double R[LT][LT];
    for (int c = 0; c < LT; c++) {
        g_lambda[c] = (float)Tt[c][c];
        for (int a = 0; a < LT; a++) {
            R[c][a] = U[a][c] * sv[a];
            g_R[c * LT + a] = (float)R[c][a];
        }
    }
    for (int c = 0; c < LT; c++)
        for (int b = 0; b < LT; b++) {
            double m = 0.0;
            for (int a = 0; a < LT; a++) m += R[c][a] * T[a][b];
            g_M[c * LT + b] = (float)m;
        }
    for (int a = 0; a < LT; a++) {
        for (int b = 0; b < LT; b++) g_Tm[a * LT + b] = (float)T[a][b];
        g_noise[a] = (float)exp((double)log_noise[a]);
    }
}

// =====================================================================
// RBF kernels. mode 0: Cxx ; mode 1: Cx + replicate into B ; mode 2: A_c
// =====================================================================
__global__ void k_rbf(const float* __restrict__ X1, const float* __restrict__ X2,
                      const float* __restrict__ log_ls, int mode)
{
    __shared__ float xs1[16][8];
    __shared__ float xs2[16][8];
    int tid = threadIdx.x;
    int bx = blockIdx.x, by = blockIdx.y;
    if (tid < 128) {
        xs1[tid >> 3][tid & 7] = X1[(by * 16 + (tid >> 3)) * 8 + (tid & 7)];
    } else {
        int q = tid - 128;
        xs2[q >> 3][q & 7] = X2[(bx * 16 + (q >> 3)) * 8 + (q & 7)];
    }
    __syncthreads();
    int tx = tid & 15, ty = tid >> 4;
    float inv_ls2 = expf(-2.0f * log_ls[0]);
    float d2 = 0.0f;
#pragma unroll
    for (int d = 0; d < 8; d++) {
        float df = xs1[ty][d] - xs2[tx][d];
        d2 += df * df;
    }
    float kv = expf(-0.5f * d2 * inv_ls2);
    int i = by * 16 + ty, j = bx * 16 + tx;
    if (mode == 0) {
        g_Cxx[(size_t)i * NP + j] = kv;
    } else if (mode == 1) {
        g_Cx[(size_t)i * NP + j] = kv;
#pragma unroll
        for (int c = 0; c < LT; c++)
            g_B[(size_t)c * NP * NTOT + (size_t)i * NTOT + j] = kv;
    } else {
        float dg = (i == j) ? 1.0f : 0.0f;
#pragma unroll
        for (int c = 0; c < LT; c++)
            g_A[(size_t)c * NP * NP + (size_t)i * NP + j] = g_lambda[c] * kv + dg;
    }
}

// ytilde into column 1024 of each B_c, zero the pad columns
__global__ void k_y(const float* __restrict__ Y)
{
    int i = blockIdx.x * blockDim.x + threadIdx.x;
    if (i >= NP) return;
    float y[LT];
#pragma unroll
    for (int a = 0; a < LT; a++) y[a] = Y[i * LT + a];
#pragma unroll
    for (int c = 0; c < LT; c++) {
        float v = 0.0f;
#pragma unroll
        for (int a = 0; a < LT; a++) v += g_R[c * LT + a] * y[a];
        size_t base = (size_t)c * NP * NTOT + (size_t)i * NTOT;
        g_B[base + 1024] = v;
        for (int p = 1025; p < NTOT; p++) g_B[base + p] = 0.0f;
    }
}

// =====================================================================
// potf2: factor 64x64 diagonal block (lower Cholesky) + produce L^{-1}
// =====================================================================
__global__ void k_potf2(int kb)
{
    int c = blockIdx.z;
    float* Ad = g_A + (size_t)c * NP * NP + (size_t)kb * 64 * NP + (size_t)kb * 64;
    float* Li = g_Linv + ((size_t)c * NKB + kb) * 64 * 64;
    __shared__ float s[64][65];
    __shared__ float vi[64][65];
    int tid = threadIdx.x;  // 256
    for (int p = tid; p < 64 * 64; p += 256) {
        int r = p >> 6, q = p & 63;
        s[r][q] = Ad[(size_t)r * NP + q];
        vi[r][q] = (r == q) ? 1.0f : 0.0f;
    }
    __syncthreads();
    for (int j = 0; j < 64; j++) {
        if (tid == 0) s[j][j] = sqrtf(s[j][j]);
        __syncthreads();
        float d = 1.0f / s[j][j];
        if (tid < 64) {
            if (tid > j) s[tid][j] *= d;
            if (tid <= j) vi[j][tid] *= d;
        }
        __syncthreads();
        int w = 63 - j;
        for (int p = tid; p < w * w; p += 256) {
            int i = j + 1 + p / w;
            int t = j + 1 + p % w;
            s[i][t] -= s[i][j] * s[t][j];
        }
        int h = j + 1;
        for (int p = tid; p < w * h; p += 256) {
            int i = j + 1 + p / h;
            int t = p % h;
            vi[i][t] -= s[i][j] * vi[j][t];
        }
        __syncthreads();
    }
    for (int p = tid; p < 64 * 64; p += 256) {
        int r = p >> 6, q = p & 63;
        if (q <= r) Ad[(size_t)r * NP + q] = s[r][q];
        Li[p] = vi[r][q];
    }
}

// =====================================================================
// Generic tiled SGEMM: C = alpha * op(A)*op(B) + beta * C
// 64x64 tiles, K-tile 16, 256 threads, 4x4 micro. Dims multiples of 64/16.
// =====================================================================
template <int TA, int TB>
__global__ void gemm_k(const float* __restrict__ A, const float* __restrict__ B,
                       float* __restrict__ C, int M, int Nn, int K,
                       int lda, int ldb, int ldc, float alpha, float beta,
                       long long sA, long long sB, long long sC, int lower_only)
{
    A += (size_t)blockIdx.z * sA;
    B += (size_t)blockIdx.z * sB;
    C += (size_t)blockIdx.z * sC;
    int mb = blockIdx.y * 64;
    int nb = blockIdx.x * 64;
    if (lower_only && nb >= mb + 64) return;
    __shared__ float As[16][68];
    __shared__ float Bs[16][68];
    int tid = threadIdx.x;
    int tx = tid & 15, ty = tid >> 4;
    float acc[4][4];
#pragma unroll
    for (int i = 0; i < 4; i++)
#pragma unroll
        for (int j = 0; j < 4; j++) acc[i][j] = 0.0f;

    for (int k0 = 0; k0 < K; k0 += 16) {
        if (TA == 0) {
            int kl = tid & 15, ml = tid >> 4;
#pragma unroll
            for (int p = 0; p < 4; p++)
                As[kl][ml + p * 16] = A[(size_t)(mb + ml + p * 16) * lda + (k0 + kl)];
        } else {
            int ml = tid & 63, kl = tid >> 6;
#pragma unroll
            for (int p = 0; p < 4; p++)
                As[kl + p * 4][ml] = A[(size_t)(k0 + kl + p * 4) * lda + (mb + ml)];
        }
        if (TB == 0) {
            int nl = tid & 63, kl = tid >> 6;
#pragma unroll
            for (int p = 0; p < 4; p++)
                Bs[kl + p * 4][nl] = B[(size_t)(k0 + kl + p * 4) * ldb + (nb + nl)];
        } else {
            int kl = tid & 15, nl = tid >> 4;
#pragma unroll
            for (int p = 0; p < 4; p++)
                Bs[kl][nl + p * 16] = B[(size_t)(nb + nl + p * 16) * ldb + (k0 + kl)];
        }
        __syncthreads();
#pragma unroll
        for (int kk = 0; kk < 16; kk++) {
            float4 av = *(const float4*)&As[kk][ty * 4];
            float4 bv = *(const float4*)&Bs[kk][tx * 4];
            float a_[4] = {av.x, av.y, av.z, av.w};
            float b_[4] = {bv.x, bv.y, bv.z, bv.w};
#pragma unroll
            for (int i = 0; i < 4; i++)
#pragma unroll
                for (int j = 0; j < 4; j++) acc[i][j] += a_[i] * b_[j];
        }
        __syncthreads();
    }
#pragma unroll
    for (int i = 0; i < 4; i++) {
        size_t row = (size_t)(mb + ty * 4 + i);
#pragma unroll
        for (int j = 0; j < 4; j++) {
            size_t idx = row * ldc + (nb + tx * 4 + j);
            float v = alpha * acc[i][j];
            if (beta != 0.0f) v += beta * C[idx];
            C[idx] = v;
        }
    }
}

// =====================================================================
// Final outputs
// =====================================================================
__global__ void k_fmean(float* __restrict__ out)
{
    int idx = blockIdx.x * blockDim.x + threadIdx.x;
    if (idx >= 4096) return;
    int b = idx >> 10, j = idx & 1023;
    float v = 0.0f;
#pragma unroll
    for (int c = 0; c < LT; c++)
        v += g_M[c * LT + b] * g_H[(size_t)c * NP * NTOT + (size_t)j * NTOT + 1024];
    out[OFF_FMEAN + idx] = v;
    out[OFF_OUT4 + (size_t)j * LT + b] = v;
}

__global__ void k_output(float* __restrict__ out)
{
    size_t t = (size_t)blockIdx.x * blockDim.x + threadIdx.x;
    if (t >= (size_t)4096 * 1024) return;
    int g = (int)(t & 1023);      // column group (4 cols)
    size_t ig = t >> 10;          // global row 0..4095
    int a = (int)(ig >> 10);
    int i = (int)(ig & 1023);
    int b = g >> 8;
    int j0 = (g & 255) << 2;
    float4 cxx = *(const float4*)&g_Cxx[(size_t)i * NP + j0];
    float Tab = g_Tm[a * LT + b];
    float4 acc;
    acc.x = Tab * cxx.x;
    acc.y = Tab * cxx.y;
    acc.z = Tab * cxx.z;
    acc.w = Tab * cxx.w;
#pragma unroll
    for (int c = 0; c < LT; c++) {
        float mm = g_M[c * LT + a] * g_M[c * LT + b];
        float4 h = *(const float4*)&g_H[(size_t)c * NP * NTOT + (size_t)i * NTOT + j0];
        acc.x -= mm * h.x;
        acc.y -= mm * h.y;
        acc.z -= mm * h.z;
        acc.w -= mm * h.w;
    }
    size_t col0 = (size_t)b * 1024 + j0;
    *(float4*)&out[OFF_FVAR + ig * 4096 + col0] = acc;
    float4 nz = make_float4(0.f, 0.f, 0.f, 0.f);
    if (ig >= col0 && ig < col0 + 4) {
        float nv = g_noise[a];
        int jj = (int)(ig - col0);
        if (jj == 0) nz.x = nv;
        else if (jj == 1) nz.y = nv;
        else if (jj == 2) nz.z = nv;
        else nz.w = nv;
    }
    *(float4*)&out[OFF_NOISE + ig * 4096 + col0] = nz;
}

// =====================================================================
// Host side
// =====================================================================
static void gemm(int TA, int TB, const float* A, const float* B, float* C,
                 int M, int Nn, int K, int lda, int ldb, int ldc,
                 float alpha, float beta, long long sA, long long sB, long long sC,
                 int batch, int lower_only)
{
    dim3 grid(Nn / 64, M / 64, batch);
    if (!TA && !TB)
        gemm_k<0, 0><<<grid, 256>>>(A, B, C, M, Nn, K, lda, ldb, ldc, alpha, beta, sA, sB, sC, lower_only);
    else if (!TA && TB)
        gemm_k<0, 1><<<grid, 256>>>(A, B, C, M, Nn, K, lda, ldb, ldc, alpha, beta, sA, sB, sC, lower_only);
    else if (TA && !TB)
        gemm_k<1, 0><<<grid, 256>>>(A, B, C, M, Nn, K, lda, ldb, ldc, alpha, beta, sA, sB, sC, lower_only);
    else
        gemm_k<1, 1><<<grid, 256>>>(A, B, C, M, Nn, K, lda, ldb, ldc, alpha, beta, sA, sB, sC, lower_only);
}

extern "C" void kernel_launch(void* const* d_in, const int* in_sizes, int n_in,
                              void* d_out, int out_size)
{
    const float* X        = (const float*)d_in[0];
    const float* test_X   = (const float*)d_in[1];
    const float* Y        = (const float*)d_in[2];
    const float* lnoise   = (const float*)d_in[3];
    const float* cfac     = (const float*)d_in[4];
    const float* lvar     = (const float*)d_in[5];
    const float* lls      = (const float*)d_in[6];
    int rank = in_sizes[4] / LT;
    float* out = (float*)d_out;

    void *pA_, *pB_, *pH_, *pCx_, *pLinv_;
    cudaGetSymbolAddress(&pA_, g_A);
    cudaGetSymbolAddress(&pB_, g_B);
    cudaGetSymbolAddress(&pH_, g_H);
    cudaGetSymbolAddress(&pCx_, g_Cx);
    cudaGetSymbolAddress(&pLinv_, g_Linv);
    float* pA = (float*)pA_;
    float* pB = (float*)pB_;
    float* pH = (float*)pH_;
    float* pCx = (float*)pCx_;
    float* pLinv = (float*)pLinv_;

    const long long strA = (long long)NP * NP;
    const long long strB = (long long)NP * NTOT;
    const long long strL = (long long)NKB * 64 * 64;

    k_setup<<<1, 32>>>(cfac, lvar, lnoise, rank);
    dim3 rg(64, 64);
    k_rbf<<<rg, 256>>>(X, X, lls, 2);           // A_c = lambda_c*C + I
    k_rbf<<<rg, 256>>>(X, test_X, lls, 1);      // Cx + replicate into B_c
    k_rbf<<<rg, 256>>>(test_X, test_X, lls, 0); // Cxx
    k_y<<<(NP + 255) / 256, 256>>>(Y);

    // ---- batched blocked Cholesky with diag-block inversion ----
    for (int kb = 0; kb < NKB; kb++) {
        k_potf2<<<dim3(1, 1, LT), 256>>>(kb);
        int rem = NP - 64 * (kb + 1);
        if (rem > 0) {
            float* panel = pA + (size_t)(kb + 1) * 64 * NP + (size_t)kb * 64;
            // panel: L_panel = A_panel * Linv^T   (in-place safe)
            gemm(0, 1, panel, pLinv + (size_t)kb * 4096, panel,
                 rem, 64, 64, NP, 64, NP, 1.0f, 0.0f, strA, strL, strA, LT, 0);
            // trailing (lower only): A -= P * P^T
            float* trail = pA + (size_t)(kb + 1) * 64 * NP + (size_t)(kb + 1) * 64;
            gemm(0, 1, panel, panel, trail,
                 rem, rem, 64, NP, NP, NP, -1.0f, 1.0f, strA, strA, strA, LT, 1);
        }
    }

    // ---- forward solve: L X = B ----
    for (int kb = 0; kb < NKB; kb++) {
        float* Bk = pB + (size_t)kb * 64 * NTOT;
        gemm(0, 0, pLinv + (size_t)kb * 4096, Bk, Bk,
             64, NTOT, 64, 64, NTOT, NTOT, 1.0f, 0.0f, strL, strB, strB, LT, 0);
        int rem = NP - 64 * (kb + 1);
        if (rem > 0) {
            gemm(0, 0, pA + (size_t)(kb + 1) * 64 * NP + (size_t)kb * 64, Bk,
                 pB + (size_t)(kb + 1) * 64 * NTOT,
                 rem, NTOT, 64, NP, NTOT, NTOT, -1.0f, 1.0f, strA, strB, strB, LT, 0);
        }
    }

    // ---- backward solve: L^T P = X ----
    for (int kb = NKB - 1; kb >= 0; kb--) {
        float* Bk = pB + (size_t)kb * 64 * NTOT;
        gemm(1, 0, pLinv + (size_t)kb * 4096, Bk, Bk,
             64, NTOT, 64, 64, NTOT, NTOT, 1.0f, 0.0f, strL, strB, strB, LT, 0);
        if (kb > 0) {
            gemm(1, 0, pA + (size_t)kb * 64 * NP, Bk, pB,
                 kb * 64, NTOT, 64, NP, NTOT, NTOT, -1.0f, 1.0f, strA, strB, strB, LT, 0);
        }
    }

    // ---- H_c = Cx^T * P_c  (incl. g_c in column 1024) ----
    gemm(1, 0, pCx, pB, pH, NP, NTOT, NP, NP, NTOT, NTOT,
         1.0f, 0.0f, 0LL, strB, strB, LT, 0);

    // ---- outputs ----
    k_fmean<<<16, 256>>>(out);
    k_output<<<16384, 256>>>(out);
}

// round 3
// speedup vs baseline: 1.0250x; 1.0250x over previous
#include <cuda_runtime.h>
#include <math.h>

// Problem constants (fixed instance)
constexpr int NP   = 1024;   // N == N_ (train/test points)
constexpr int LT   = 4;      // tasks
constexpr int RNK_MAX = 8;
constexpr int NTOT = 1152;   // RHS width: 1024 Cx cols + 1 ytilde col + pad to 9*128
constexpr int NKB  = 16;     // 1024 / 64 block steps

// Output offsets (fp32 elements)
constexpr size_t OFF_FMEAN = 0;
constexpr size_t OFF_FVAR  = 4096;
constexpr size_t OFF_NOISE = OFF_FVAR + (size_t)4096 * 4096;
constexpr size_t OFF_OUT4  = OFF_NOISE + (size_t)4096 * 4096;

// -------- device scratch (static, no allocation) --------
__device__ float g_A[LT * NP * NP];          // lambda_c*C + I, then Cholesky L (lower)
__device__ float g_B[LT * NP * NTOT];        // RHS -> forward-solved P_c (and w_c in col 1024)
__device__ float g_H[LT * NP * NTOT];        // H_c = P_c^T * P_c  (col 1024 = g_c)
__device__ float g_Cxx[NP * NP];             // rbf(test_X, test_X)
__device__ float g_Linv[LT * NKB * 64 * 64]; // per-step 64x64 diag-block inverses
__device__ float g_lambda[LT];
__device__ float g_R[LT * LT];               // R = U^T Dn^{-1/2}
__device__ float g_M[LT * LT];               // M = R * T
__device__ float g_Tm[LT * LT];              // task_K
__device__ float g_noise[LT];                // exp(log_noise)

// =====================================================================
// Small setup: task_K, 4x4 Jacobi eigendecomposition, R, M (fp64)
// =====================================================================
__global__ void k_setup(const float* __restrict__ cf,
                        const float* __restrict__ log_var,
                        const float* __restrict__ log_noise,
                        int rank)
{
    if (threadIdx.x != 0) return;
    double T[LT][LT], Tt[LT][LT], U[LT][LT], sv[LT];
    for (int a = 0; a < LT; a++) sv[a] = exp(-0.5 * (double)log_noise[a]);
    for (int a = 0; a < LT; a++)
        for (int b = 0; b < LT; b++) {
            double s = 0.0;
            for (int r = 0; r < rank && r < RNK_MAX; r++)
                s += (double)cf[a * rank + r] * (double)cf[b * rank + r];
            if (a == b) s += exp((double)log_var[a]);
            T[a][b] = s;
        }
    for (int a = 0; a < LT; a++)
        for (int b = 0; b < LT; b++) {
            Tt[a][b] = sv[a] * sv[b] * T[a][b];
            U[a][b] = (a == b) ? 1.0 : 0.0;
        }
    // cyclic Jacobi
    for (int sweep = 0; sweep < 60; sweep++) {
        double off = 0.0;
        for (int p = 0; p < LT; p++)
            for (int q = p + 1; q < LT; q++) off += Tt[p][q] * Tt[p][q];
        if (off < 1e-28) break;
        for (int p = 0; p < LT; p++)
            for (int q = p + 1; q < LT; q++) {
                double apq = Tt[p][q];
                if (fabs(apq) < 1e-300) continue;
                double tau = (Tt[q][q] - Tt[p][p]) / (2.0 * apq);
                double tt = ((tau >= 0.0) ? 1.0 : -1.0) / (fabs(tau) + sqrt(1.0 + tau * tau));
                double cc = 1.0 / sqrt(1.0 + tt * tt);
                double ss = tt * cc;
                for (int k = 0; k < LT; k++) {
                    double akp = Tt[k][p], akq = Tt[k][q];
                    Tt[k][p] = cc * akp - ss * akq;
                    Tt[k][q] = ss * akp + cc * akq;
                }
                for (int k = 0; k < LT; k++) {
                    double apk = Tt[p][k], aqk = Tt[q][k];
                    Tt[p][k] = cc * apk - ss * aqk;
                    Tt[q][k] = ss * apk + cc * aqk;
                }
                for (int k = 0; k < LT; k++) {
                    double ukp = U[k][p], ukq = U[k][q];
                    U[k][p] = cc * ukp - ss * ukq;
                    U[k][q] = ss * ukp + cc * ukq;
                }
            }
    }
    double R[LT][LT];
    for (int c = 0; c < LT; c++) {
        g_lambda[c] = (float)Tt[c][c];
        for (int a = 0; a < LT; a++) {
            R[c][a] = U[a][c] * sv[a];
            g_R[c * LT + a] = (float)R[c][a];
        }
    }
    for (int c = 0; c < LT; c++)
        for (int b = 0; b < LT; b++) {
            double m = 0.0;
            for (int a = 0; a < LT; a++) m += R[c][a] * T[a][b];
            g_M[c * LT + b] = (float)m;
        }
    for (int a = 0; a < LT; a++) {
        for (int b = 0; b < LT; b++) g_Tm[a * LT + b] = (float)T[a][b];
        g_noise[a] = (float)exp((double)log_noise[a]);
    }
}

// =====================================================================
// RBF kernels. mode 0: Cxx ; mode 1: Cx into B ; mode 2: A_c
// =====================================================================
__global__ void k_rbf(const float* __restrict__ X1, const float* __restrict__ X2,
                      const float* __restrict__ log_ls, int mode)
{
    __shared__ float xs1[16][8];
    __shared__ float xs2[16][8];
    int tid = threadIdx.x;
    int bx = blockIdx.x, by = blockIdx.y;
    if (tid < 128) {
        xs1[tid >> 3][tid & 7] = X1[(by * 16 + (tid >> 3)) * 8 + (tid & 7)];
    } else {
        int q = tid - 128;
        xs2[q >> 3][q & 7] = X2[(bx * 16 + (q >> 3)) * 8 + (q & 7)];
    }
    __syncthreads();
    int tx = tid & 15, ty = tid >> 4;
    float inv_ls2 = expf(-2.0f * log_ls[0]);
    float d2 = 0.0f;
#pragma unroll
    for (int d = 0; d < 8; d++) {
        float df = xs1[ty][d] - xs2[tx][d];
        d2 += df * df;
    }
    float kv = expf(-0.5f * d2 * inv_ls2);
    int i = by * 16 + ty, j = bx * 16 + tx;
    if (mode == 0) {
        g_Cxx[(size_t)i * NP + j] = kv;
    } else if (mode == 1) {
#pragma unroll
        for (int c = 0; c < LT; c++)
            g_B[(size_t)c * NP * NTOT + (size_t)i * NTOT + j] = kv;
    } else {
        float dg = (i == j) ? 1.0f : 0.0f;
#pragma unroll
        for (int c = 0; c < LT; c++)
            g_A[(size_t)c * NP * NP + (size_t)i * NP + j] = g_lambda[c] * kv + dg;
    }
}

// ytilde into column 1024 of each B_c, zero the pad columns
__global__ void k_y(const float* __restrict__ Y)
{
    int i = blockIdx.x * blockDim.x + threadIdx.x;
    if (i >= NP) return;
    float y[LT];
#pragma unroll
    for (int a = 0; a < LT; a++) y[a] = Y[i * LT + a];
#pragma unroll
    for (int c = 0; c < LT; c++) {
        float v = 0.0f;
#pragma unroll
        for (int a = 0; a < LT; a++) v += g_R[c * LT + a] * y[a];
        size_t base = (size_t)c * NP * NTOT + (size_t)i * NTOT;
        g_B[base + 1024] = v;
        for (int p = 1025; p < NTOT; p++) g_B[base + p] = 0.0f;
    }
}

// =====================================================================
// potf2: factor 64x64 diagonal block (lower Cholesky) + produce L^{-1}
// =====================================================================
__global__ void k_potf2(int kb)
{
    int c = blockIdx.z;
    float* Ad = g_A + (size_t)c * NP * NP + (size_t)kb * 64 * NP + (size_t)kb * 64;
    float* Li = g_Linv + ((size_t)c * NKB + kb) * 64 * 64;
    __shared__ float s[64][65];
    __shared__ float vi[64][65];
    int tid = threadIdx.x;  // 256
    for (int p = tid; p < 64 * 64; p += 256) {
        int r = p >> 6, q = p & 63;
        s[r][q] = Ad[(size_t)r * NP + q];
        vi[r][q] = (r == q) ? 1.0f : 0.0f;
    }
    __syncthreads();
    for (int j = 0; j < 64; j++) {
        if (tid == 0) s[j][j] = sqrtf(s[j][j]);
        __syncthreads();
        float d = 1.0f / s[j][j];
        if (tid < 64) {
            if (tid > j) s[tid][j] *= d;
            if (tid <= j) vi[j][tid] *= d;
        }
        __syncthreads();
        int w = 63 - j;
        for (int p = tid; p < w * w; p += 256) {
            int i = j + 1 + p / w;
            int t = j + 1 + p % w;
            s[i][t] -= s[i][j] * s[t][j];
        }
        int h = j + 1;
        for (int p = tid; p < w * h; p += 256) {
            int i = j + 1 + p / h;
            int t = p % h;
            vi[i][t] -= s[i][j] * vi[j][t];
        }
        __syncthreads();
    }
    for (int p = tid; p < 64 * 64; p += 256) {
        int r = p >> 6, q = p & 63;
        if (q <= r) Ad[(size_t)r * NP + q] = s[r][q];
        Li[p] = vi[r][q];
    }
}

// =====================================================================
// Small 64x64-tile SGEMM (used for diag solves + panel scaling)
// =====================================================================
template <int TA, int TB>
__global__ void gemm64_k(const float* __restrict__ A, const float* __restrict__ B,
                         float* __restrict__ C, int M, int Nn, int K,
                         int lda, int ldb, int ldc, float alpha, float beta,
                         long long sA, long long sB, long long sC)
{
    A += (size_t)blockIdx.z * sA;
    B += (size_t)blockIdx.z * sB;
    C += (size_t)blockIdx.z * sC;
    int mb = blockIdx.y * 64;
    int nb = blockIdx.x * 64;
    __shared__ float As[16][68];
    __shared__ float Bs[16][68];
    int tid = threadIdx.x;
    int tx = tid & 15, ty = tid >> 4;
    float acc[4][4];
#pragma unroll
    for (int i = 0; i < 4; i++)
#pragma unroll
        for (int j = 0; j < 4; j++) acc[i][j] = 0.0f;

    for (int k0 = 0; k0 < K; k0 += 16) {
        if (TA == 0) {
            int kl = tid & 15, ml = tid >> 4;
#pragma unroll
            for (int p = 0; p < 4; p++)
                As[kl][ml + p * 16] = A[(size_t)(mb + ml + p * 16) * lda + (k0 + kl)];
        } else {
            int ml = tid & 63, kl = tid >> 6;
#pragma unroll
            for (int p = 0; p < 4; p++)
                As[kl + p * 4][ml] = A[(size_t)(k0 + kl + p * 4) * lda + (mb + ml)];
        }
        if (TB == 0) {
            int nl = tid & 63, kl = tid >> 6;
#pragma unroll
            for (int p = 0; p < 4; p++)
                Bs[kl + p * 4][nl] = B[(size_t)(k0 + kl + p * 4) * ldb + (nb + nl)];
        } else {
            int kl = tid & 15, nl = tid >> 4;
#pragma unroll
            for (int p = 0; p < 4; p++)
                Bs[kl][nl + p * 16] = B[(size_t)(nb + nl + p * 16) * ldb + (k0 + kl)];
        }
        __syncthreads();
#pragma unroll
        for (int kk = 0; kk < 16; kk++) {
            float4 av = *(const float4*)&As[kk][ty * 4];
            float4 bv = *(const float4*)&Bs[kk][tx * 4];
            float a_[4] = {av.x, av.y, av.z, av.w};
            float b_[4] = {bv.x, bv.y, bv.z, bv.w};
#pragma unroll
            for (int i = 0; i < 4; i++)
#pragma unroll
                for (int j = 0; j < 4; j++) acc[i][j] += a_[i] * b_[j];
        }
        __syncthreads();
    }
#pragma unroll
    for (int i = 0; i < 4; i++) {
        size_t row = (size_t)(mb + ty * 4 + i);
#pragma unroll
        for (int j = 0; j < 4; j++) {
            size_t idx = row * ldc + (nb + tx * 4 + j);
            float v = alpha * acc[i][j];
            if (beta != 0.0f) v += beta * C[idx];
            C[idx] = v;
        }
    }
}

// =====================================================================
// Big 128x128-tile SGEMM, 8x8 micro, 256 threads.
// mode: 0=full, 1=lower tiles only (nb<=mb), 2=lower tiles or last col tile
// =====================================================================
template <int TA, int TB>
__global__ __launch_bounds__(256, 2)
void gemm128_k(const float* __restrict__ A, const float* __restrict__ B,
               float* __restrict__ C, int M, int N, int K,
               int lda, int ldb, int ldc, float alpha, float beta,
               long long sA, long long sB, long long sC, int mode)
{
    int nb = blockIdx.x, mb = blockIdx.y;
    if (mode == 1 && nb > mb) return;
    if (mode == 2 && nb > mb && nb != (int)gridDim.x - 1) return;
    A += (size_t)blockIdx.z * sA;
    B += (size_t)blockIdx.z * sB;
    C += (size_t)blockIdx.z * sC;
    const int row0 = mb * 128, col0 = nb * 128;
    __shared__ float As[16][132];
    __shared__ float Bs[16][132];
    int tid = threadIdx.x;
    int tx = tid & 15, ty = tid >> 4;
    float acc[8][8];
#pragma unroll
    for (int i = 0; i < 8; i++)
#pragma unroll
        for (int j = 0; j < 8; j++) acc[i][j] = 0.0f;

    for (int k0 = 0; k0 < K; k0 += 16) {
        if (TA == 0) {
            int r = tid >> 2, c4 = (tid & 3) << 2;
#pragma unroll
            for (int h = 0; h < 2; h++) {
                int m = row0 + r + h * 64;
                if (m >= M) m = M - 1;
                float4 v = *(const float4*)(A + (size_t)m * lda + k0 + c4);
                As[c4 + 0][r + h * 64] = v.x;
                As[c4 + 1][r + h * 64] = v.y;
                As[c4 + 2][r + h * 64] = v.z;
                As[c4 + 3][r + h * 64] = v.w;
            }
        } else {
            int kk = tid >> 4, m8 = (tid & 15) << 3;
#pragma unroll
            for (int h = 0; h < 2; h++) {
                int m = row0 + m8 + h * 4;
                if (m + 3 < M) {
                    float4 v = *(const float4*)(A + (size_t)(k0 + kk) * lda + m);
                    *(float4*)&As[kk][m8 + h * 4] = v;
                } else {
#pragma unroll
                    for (int q = 0; q < 4; q++) {
                        int mc = m + q; if (mc >= M) mc = M - 1;
                        As[kk][m8 + h * 4 + q] = A[(size_t)(k0 + kk) * lda + mc];
                    }
                }
            }
        }
        if (TB == 0) {
            int kk = tid >> 4, n8 = (tid & 15) << 3;
#pragma unroll
            for (int h = 0; h < 2; h++) {
                int n = col0 + n8 + h * 4;
                if (n + 3 < N) {
                    float4 v = *(const float4*)(B + (size_t)(k0 + kk) * ldb + n);
                    *(float4*)&Bs[kk][n8 + h * 4] = v;
                } else {
#pragma unroll
                    for (int q = 0; q < 4; q++) {
                        int nc = n + q; if (nc >= N) nc = N - 1;
                        Bs[kk][n8 + h * 4 + q] = B[(size_t)(k0 + kk) * ldb + nc];
                    }
                }
            }
        } else {
            int r = tid >> 2, c4 = (tid & 3) << 2;
#pragma unroll
            for (int h = 0; h < 2; h++) {
                int n = col0 + r + h * 64;
                if (n >= N) n = N - 1;
                float4 v = *(const float4*)(B + (size_t)n * ldb + k0 + c4);
                Bs[c4 + 0][r + h * 64] = v.x;
                Bs[c4 + 1][r + h * 64] = v.y;
                Bs[c4 + 2][r + h * 64] = v.z;
                Bs[c4 + 3][r + h * 64] = v.w;
            }
        }
        __syncthreads();
#pragma unroll
        for (int kk = 0; kk < 16; kk++) {
            float4 a0 = *(const float4*)&As[kk][ty * 8];
            float4 a1 = *(const float4*)&As[kk][ty * 8 + 4];
            float4 b0 = *(const float4*)&Bs[kk][tx * 8];
            float4 b1 = *(const float4*)&Bs[kk][tx * 8 + 4];
            float av[8] = {a0.x, a0.y, a0.z, a0.w, a1.x, a1.y, a1.z, a1.w};
            float bv[8] = {b0.x, b0.y, b0.z, b0.w, b1.x, b1.y, b1.z, b1.w};
#pragma unroll
            for (int i = 0; i < 8; i++)
#pragma unroll
                for (int j = 0; j < 8; j++) acc[i][j] += av[i] * bv[j];
        }
        __syncthreads();
    }
#pragma unroll
    for (int i = 0; i < 8; i++) {
        int m = row0 + ty * 8 + i;
        if (m >= M) continue;
#pragma unroll
        for (int j = 0; j < 8; j += 4) {
            int n = col0 + tx * 8 + j;
            if (n >= N) continue;
            float* p = C + (size_t)m * ldc + n;
            float4 v;
            v.x = alpha * acc[i][j + 0];
            v.y = alpha * acc[i][j + 1];
            v.z = alpha * acc[i][j + 2];
            v.w = alpha * acc[i][j + 3];
            if (beta != 0.0f) {
                float4 o = *(const float4*)p;
                v.x += beta * o.x; v.y += beta * o.y;
                v.z += beta * o.z; v.w += beta * o.w;
            }
            *(float4*)p = v;
        }
    }
}

// =====================================================================
// Symmetrize H: copy lower triangle -> upper (cols < 1024 only)
// =====================================================================
__global__ void k_symH()
{
    int tc = blockIdx.x, tr = blockIdx.y;  // 32-wide tiles
    if (tc < tr) return;                   // only diagonal + upper dest tiles
    int c = blockIdx.z;
    float* H = g_H + (size_t)c * NP * NTOT;
    __shared__ float s[32][33];
    int x = threadIdx.x, y0 = threadIdx.y;  // (32, 8)
    // source tile: rows tc*32.., cols tr*32..  (lower triangle)
    for (int yy = y0; yy < 32; yy += 8)
        s[yy][x] = H[(size_t)(tc * 32 + yy) * NTOT + tr * 32 + x];
    __syncthreads();
    // dest tile: rows tr*32.., cols tc*32..: H[i][j] = H[j][i]
    for (int yy = y0; yy < 32; yy += 8) {
        int i = tr * 32 + yy, j = tc * 32 + x;
        if (j > i) H[(size_t)i * NTOT + j] = s[x][yy];
    }
}

// =====================================================================
// Final outputs
// =====================================================================
__global__ void k_fmean(float* __restrict__ out)
{
    int idx = blockIdx.x * blockDim.x + threadIdx.x;
    if (idx >= 4096) return;
    int b = idx >> 10, j = idx & 1023;
    float v = 0.0f;
#pragma unroll
    for (int c = 0; c < LT; c++)
        v += g_M[c * LT + b] * g_H[(size_t)c * NP * NTOT + (size_t)j * NTOT + 1024];
    out[OFF_FMEAN + idx] = v;
    out[OFF_OUT4 + (size_t)j * LT + b] = v;
}

__global__ void k_output(float* __restrict__ out)
{
    size_t t = (size_t)blockIdx.x * blockDim.x + threadIdx.x;
    if (t >= (size_t)4096 * 1024) return;
    int g = (int)(t & 1023);      // column group (4 cols)
    size_t ig = t >> 10;          // global row 0..4095
    int a = (int)(ig >> 10);
    int i = (int)(ig & 1023);
    int b = g >> 8;
    int j0 = (g & 255) << 2;
    float4 cxx = *(const float4*)&g_Cxx[(size_t)i * NP + j0];
    float Tab = g_Tm[a * LT + b];
    float4 acc;
    acc.x = Tab * cxx.x;
    acc.y = Tab * cxx.y;
    acc.z = Tab * cxx.z;
    acc.w = Tab * cxx.w;
#pragma unroll
    for (int c = 0; c < LT; c++) {
        float mm = g_M[c * LT + a] * g_M[c * LT + b];
        float4 h = *(const float4*)&g_H[(size_t)c * NP * NTOT + (size_t)i * NTOT + j0];
        acc.x -= mm * h.x;
        acc.y -= mm * h.y;
        acc.z -= mm * h.z;
        acc.w -= mm * h.w;
    }
    size_t col0 = (size_t)b * 1024 + j0;
    *(float4*)&out[OFF_FVAR + ig * 4096 + col0] = acc;
    float4 nz = make_float4(0.f, 0.f, 0.f, 0.f);
    if (ig >= col0 && ig < col0 + 4) {
        float nv = g_noise[a];
        int jj = (int)(ig - col0);
        if (jj == 0) nz.x = nv;
        else if (jj == 1) nz.y = nv;
        else if (jj == 2) nz.z = nv;
        else nz.w = nv;
    }
    *(float4*)&out[OFF_NOISE + ig * 4096 + col0] = nz;
}

// =====================================================================
// Host side
// =====================================================================
static void gemm64(int TA, int TB, const float* A, const float* B, float* C,
                   int M, int Nn, int K, int lda, int ldb, int ldc,
                   float alpha, float beta, long long sA, long long sB, long long sC,
                   int batch)
{
    dim3 grid(Nn / 64, M / 64, batch);
    if (!TA && !TB)
        gemm64_k<0, 0><<<grid, 256>>>(A, B, C, M, Nn, K, lda, ldb, ldc, alpha, beta, sA, sB, sC);
    else
        gemm64_k<0, 1><<<grid, 256>>>(A, B, C, M, Nn, K, lda, ldb, ldc, alpha, beta, sA, sB, sC);
}

static void gemm128(int TA, int TB, const float* A, const float* B, float* C,
                    int M, int N, int K, int lda, int ldb, int ldc,
                    float alpha, float beta, long long sA, long long sB, long long sC,
                    int batch, int mode)
{
    dim3 grid((N + 127) / 128, (M + 127) / 128, batch);
    if (!TA && !TB)
        gemm128_k<0, 0><<<grid, 256>>>(A, B, C, M, N, K, lda, ldb, ldc, alpha, beta, sA, sB, sC, mode);
    else if (!TA && TB)
        gemm128_k<0, 1><<<grid, 256>>>(A, B, C, M, N, K, lda, ldb, ldc, alpha, beta, sA, sB, sC, mode);
    else
        gemm128_k<1, 0><<<grid, 256>>>(A, B, C, M, N, K, lda, ldb, ldc, alpha, beta, sA, sB, sC, mode);
}

extern "C" void kernel_launch(void* const* d_in, const int* in_sizes, int n_in,
                              void* d_out, int out_size)
{
    const float* X        = (const float*)d_in[0];
    const float* test_X   = (const float*)d_in[1];
    const float* Y        = (const float*)d_in[2];
    const float* lnoise   = (const float*)d_in[3];
    const float* cfac     = (const float*)d_in[4];
    const float* lvar     = (const float*)d_in[5];
    const float* lls      = (const float*)d_in[6];
    int rank = in_sizes[4] / LT;
    float* out = (float*)d_out;

    void *pA_, *pB_, *pH_, *pLinv_;
    cudaGetSymbolAddress(&pA_, g_A);
    cudaGetSymbolAddress(&pB_, g_B);
    cudaGetSymbolAddress(&pH_, g_H);
    cudaGetSymbolAddress(&pLinv_, g_Linv);
    float* pA = (float*)pA_;
    float* pB = (float*)pB_;
    float* pH = (float*)pH_;
    float* pLinv = (float*)pLinv_;

    const long long strA = (long long)NP * NP;
    const long long strB = (long long)NP * NTOT;
    const long long strL = (long long)NKB * 64 * 64;

    k_setup<<<1, 32>>>(cfac, lvar, lnoise, rank);
    dim3 rg(64, 64);
    k_rbf<<<rg, 256>>>(X, X, lls, 2);           // A_c = lambda_c*C + I
    k_rbf<<<rg, 256>>>(X, test_X, lls, 1);      // Cx into B_c
    k_rbf<<<rg, 256>>>(test_X, test_X, lls, 0); // Cxx
    k_y<<<(NP + 255) / 256, 256>>>(Y);

    // ---- batched blocked Cholesky with diag-block inversion ----
    for (int kb = 0; kb < NKB; kb++) {
        k_potf2<<<dim3(1, 1, LT), 256>>>(kb);
        int rem = NP - 64 * (kb + 1);
        if (rem > 0) {
            float* panel = pA + (size_t)(kb + 1) * 64 * NP + (size_t)kb * 64;
            // panel: L_panel = A_panel * Linv^T   (in-place safe)
            gemm64(0, 1, panel, pLinv + (size_t)kb * 4096, panel,
                   rem, 64, 64, NP, 64, NP, 1.0f, 0.0f, strA, strL, strA, LT);
            // trailing (lower only): A -= P * P^T
            float* trail = pA + (size_t)(kb + 1) * 64 * NP + (size_t)(kb + 1) * 64;
            gemm128(0, 1, panel, panel, trail,
                    rem, rem, 64, NP, NP, NP, -1.0f, 1.0f, strA, strA, strA, LT, 1);
        }
    }

    // ---- forward solve: L P = B  (no backward solve needed: H = P^T P) ----
    for (int kb = 0; kb < NKB; kb++) {
        float* Bk = pB + (size_t)kb * 64 * NTOT;
        gemm64(0, 0, pLinv + (size_t)kb * 4096, Bk, Bk,
               64, NTOT, 64, 64, NTOT, NTOT, 1.0f, 0.0f, strL, strB, strB, LT);
        int rem = NP - 64 * (kb + 1);
        if (rem > 0) {
            gemm128(0, 0, pA + (size_t)(kb + 1) * 64 * NP + (size_t)kb * 64, Bk,
                    pB + (size_t)(kb + 1) * 64 * NTOT,
                    rem, NTOT, 64, NP, NTOT, NTOT, -1.0f, 1.0f, strA, strB, strB, LT, 0);
        }
    }

    // ---- H_c = P_c^T * P_c  (lower tiles + last col tile holding g_c) ----
    gemm128(1, 0, pB, pB, pH, NP, NTOT, NP, NTOT, NTOT, NTOT,
            1.0f, 0.0f, strB, strB, strB, LT, 2);
    k_symH<<<dim3(32, 32, LT), dim3(32, 8)>>>();

    // ---- outputs ----
    k_fmean<<<16, 256>>>(out);
    k_output<<<16384, 256>>>(out);
}

// round 4
// speedup vs baseline: 1.5760x; 1.5376x over previous
#include <cuda_runtime.h>
#include <math.h>

// Problem constants (fixed instance)
constexpr int NP   = 1024;   // N == N_ (train/test points)
constexpr int LT   = 4;      // tasks
constexpr int RNK_MAX = 8;
constexpr int NTOT = 1152;   // RHS width: 1024 Cx cols + 1 ytilde col + pad to 9*128
constexpr int NKB  = 16;     // 1024 / 64 block steps

// Output offsets (fp32 elements)
constexpr size_t OFF_FMEAN = 0;
constexpr size_t OFF_FVAR  = 4096;
constexpr size_t OFF_NOISE = OFF_FVAR + (size_t)4096 * 4096;
constexpr size_t OFF_OUT4  = OFF_NOISE + (size_t)4096 * 4096;

// -------- device scratch (static, no allocation) --------
__device__ float g_A[LT * NP * NP];          // lambda_c*C + I, then Cholesky L (lower)
__device__ float g_B[LT * NP * NTOT];        // RHS -> forward-solved P_c (and w_c in col 1024)
__device__ float g_H[LT * NP * NTOT];        // H_c = P_c^T * P_c  (col 1024 = g_c)
__device__ float g_Cxx[NP * NP];             // rbf(test_X, test_X)
__device__ float g_Linv[LT * NKB * 64 * 64]; // per-step 64x64 diag-block inverses
__device__ float g_lambda[LT];
__device__ float g_R[LT * LT];               // R = U^T Dn^{-1/2}
__device__ float g_M[LT * LT];               // M = R * T
__device__ float g_Tm[LT * LT];              // task_K
__device__ float g_noise[LT];                // exp(log_noise)

// =====================================================================
// Small setup: task_K, 4x4 Jacobi eigendecomposition, R, M (fp64)
// =====================================================================
__global__ void k_setup(const float* __restrict__ cf,
                        const float* __restrict__ log_var,
                        const float* __restrict__ log_noise,
                        int rank)
{
    if (threadIdx.x != 0) return;
    double T[LT][LT], Tt[LT][LT], U[LT][LT], sv[LT];
    for (int a = 0; a < LT; a++) sv[a] = exp(-0.5 * (double)log_noise[a]);
    for (int a = 0; a < LT; a++)
        for (int b = 0; b < LT; b++) {
            double s = 0.0;
            for (int r = 0; r < rank && r < RNK_MAX; r++)
                s += (double)cf[a * rank + r] * (double)cf[b * rank + r];
            if (a == b) s += exp((double)log_var[a]);
            T[a][b] = s;
        }
    for (int a = 0; a < LT; a++)
        for (int b = 0; b < LT; b++) {
            Tt[a][b] = sv[a] * sv[b] * T[a][b];
            U[a][b] = (a == b) ? 1.0 : 0.0;
        }
    for (int sweep = 0; sweep < 60; sweep++) {
        double off = 0.0;
        for (int p = 0; p < LT; p++)
            for (int q = p + 1; q < LT; q++) off += Tt[p][q] * Tt[p][q];
        if (off < 1e-28) break;
        for (int p = 0; p < LT; p++)
            for (int q = p + 1; q < LT; q++) {
                double apq = Tt[p][q];
                if (fabs(apq) < 1e-300) continue;
                double tau = (Tt[q][q] - Tt[p][p]) / (2.0 * apq);
                double tt = ((tau >= 0.0) ? 1.0 : -1.0) / (fabs(tau) + sqrt(1.0 + tau * tau));
                double cc = 1.0 / sqrt(1.0 + tt * tt);
                double ss = tt * cc;
                for (int k = 0; k < LT; k++) {
                    double akp = Tt[k][p], akq = Tt[k][q];
                    Tt[k][p] = cc * akp - ss * akq;
                    Tt[k][q] = ss * akp + cc * akq;
                }
                for (int k = 0; k < LT; k++) {
                    double apk = Tt[p][k], aqk = Tt[q][k];
                    Tt[p][k] = cc * apk - ss * aqk;
                    Tt[q][k] = ss * apk + cc * aqk;
                }
                for (int k = 0; k < LT; k++) {
                    double ukp = U[k][p], ukq = U[k][q];
                    U[k][p] = cc * ukp - ss * ukq;
                    U[k][q] = ss * ukp + cc * ukq;
                }
            }
    }
    double R[LT][LT];
    for (int c = 0; c < LT; c++) {
        g_lambda[c] = (float)Tt[c][c];
        for (int a = 0; a < LT; a++) {
            R[c][a] = U[a][c] * sv[a];
            g_R[c * LT + a] = (float)R[c][a];
        }
    }
    for (int c = 0; c < LT; c++)
        for (int b = 0; b < LT; b++) {
            double m = 0.0;
            for (int a = 0; a < LT; a++) m += R[c][a] * T[a][b];
            g_M[c * LT + b] = (float)m;
        }
    for (int a = 0; a < LT; a++) {
        for (int b = 0; b < LT; b++) g_Tm[a * LT + b] = (float)T[a][b];
        g_noise[a] = (float)exp((double)log_noise[a]);
    }
}

// =====================================================================
// RBF kernels. mode 0: Cxx ; mode 1: Cx into B ; mode 2: A_c
// =====================================================================
__global__ void k_rbf(const float* __restrict__ X1, const float* __restrict__ X2,
                      const float* __restrict__ log_ls, int mode)
{
    __shared__ float xs1[16][8];
    __shared__ float xs2[16][8];
    int tid = threadIdx.x;
    int bx = blockIdx.x, by = blockIdx.y;
    if (tid < 128) {
        xs1[tid >> 3][tid & 7] = X1[(by * 16 + (tid >> 3)) * 8 + (tid & 7)];
    } else {
        int q = tid - 128;
        xs2[q >> 3][q & 7] = X2[(bx * 16 + (q >> 3)) * 8 + (q & 7)];
    }
    __syncthreads();
    int tx = tid & 15, ty = tid >> 4;
    float inv_ls2 = expf(-2.0f * log_ls[0]);
    float d2 = 0.0f;
#pragma unroll
    for (int d = 0; d < 8; d++) {
        float df = xs1[ty][d] - xs2[tx][d];
        d2 += df * df;
    }
    float kv = expf(-0.5f * d2 * inv_ls2);
    int i = by * 16 + ty, j = bx * 16 + tx;
    if (mode == 0) {
        g_Cxx[(size_t)i * NP + j] = kv;
    } else if (mode == 1) {
#pragma unroll
        for (int c = 0; c < LT; c++)
            g_B[(size_t)c * NP * NTOT + (size_t)i * NTOT + j] = kv;
    } else {
        float dg = (i == j) ? 1.0f : 0.0f;
#pragma unroll
        for (int c = 0; c < LT; c++)
            g_A[(size_t)c * NP * NP + (size_t)i * NP + j] = g_lambda[c] * kv + dg;
    }
}

// ytilde into column 1024 of each B_c, zero the pad columns
__global__ void k_y(const float* __restrict__ Y)
{
    int i = blockIdx.x * blockDim.x + threadIdx.x;
    if (i >= NP) return;
    float y[LT];
#pragma unroll
    for (int a = 0; a < LT; a++) y[a] = Y[i * LT + a];
#pragma unroll
    for (int c = 0; c < LT; c++) {
        float v = 0.0f;
#pragma unroll
        for (int a = 0; a < LT; a++) v += g_R[c * LT + a] * y[a];
        size_t base = (size_t)c * NP * NTOT + (size_t)i * NTOT;
        g_B[base + 1024] = v;
        for (int p = 1025; p < NTOT; p++) g_B[base + p] = 0.0f;
    }
}

// =====================================================================
// potf2: factor 64x64 diagonal block + produce L^{-1}.
// No div/mod; fixed row-per-thread; 2 barriers per column.
// =====================================================================
__global__ void k_potf2(int kb)
{
    int c = blockIdx.z;
    float* Ad = g_A + (size_t)c * NP * NP + (size_t)kb * 64 * NP + (size_t)kb * 64;
    float* Li = g_Linv + ((size_t)c * NKB + kb) * 64 * 64;
    __shared__ float s[64][65];
    __shared__ float vi[64][65];
    __shared__ float sdiag[64];
    int tid = threadIdx.x;  // 256
    int r = tid & 63, q = tid >> 6;
    for (int p = tid; p < 64 * 64; p += 256) {
        int rr = p >> 6, qq = p & 63;
        s[rr][qq] = Ad[(size_t)rr * NP + qq];
        vi[rr][qq] = (rr == qq) ? 1.0f : 0.0f;
    }
    __syncthreads();
#pragma unroll 1
    for (int j = 0; j < 64; j++) {
        float d = rsqrtf(s[j][j]);          // redundant per-thread; s[j][j] never written
        if (q == 0 && r > j)  s[r][j] *= d;
        if (q == 1 && r <= j) vi[j][r] *= d;
        if (q == 2 && r == j) sdiag[j] = s[j][j] * d;
        __syncthreads();
        if (r > j) {
            float sij = s[r][j];
            for (int t = j + 1 + q; t < 64; t += 4)
                s[r][t] -= sij * s[t][j];
            for (int t = q; t <= j; t += 4)
                vi[r][t] -= sij * vi[j][t];
        }
        __syncthreads();
    }
    for (int p = tid; p < 64 * 64; p += 256) {
        int rr = p >> 6, qq = p & 63;
        if (qq < rr) Ad[(size_t)rr * NP + qq] = s[rr][qq];
        else if (qq == rr) Ad[(size_t)rr * NP + qq] = sdiag[rr];
        Li[p] = vi[rr][qq];
    }
}

// =====================================================================
// combo1 (per kb): one launch does
//   job A (bx < panelTiles): panel tile = A_panel(64x64-strip) * Linv^T
//   job B (bx >= panelTiles): B_kb(64 x 1152) = Linv * B_kb
// 64x64 tiles, 4x4 micro, in-place safe (writes after full K loop).
// =====================================================================
__global__ void k_combo1(int kb, int rem)
{
    int c = blockIdx.z;
    const float* Li = g_Linv + ((size_t)c * NKB + kb) * 4096;
    int panelTiles = rem >> 6;
    int bx = blockIdx.x;
    __shared__ float As[16][68];
    __shared__ float Bs[16][68];
    int tid = threadIdx.x, tx = tid & 15, ty = tid >> 4;
    float acc[4][4];
#pragma unroll
    for (int i = 0; i < 4; i++)
#pragma unroll
        for (int j = 0; j < 4; j++) acc[i][j] = 0.0f;

    const float* Aop; const float* Bop; float* Cop;
    int lda, ldb, ldc; bool tb;
    if (bx < panelTiles) {
        float* panel = g_A + (size_t)c * NP * NP + (size_t)(kb + 1) * 64 * NP + (size_t)kb * 64;
        Aop = panel + (size_t)bx * 64 * NP; lda = NP;
        Bop = Li; ldb = 64; tb = true;
        Cop = panel + (size_t)bx * 64 * NP; ldc = NP;
    } else {
        int nb = bx - panelTiles;
        float* Bk = g_B + (size_t)c * NP * NTOT + (size_t)kb * 64 * NTOT;
        Aop = Li; lda = 64; tb = false;
        Bop = Bk + nb * 64; ldb = NTOT;
        Cop = Bk + nb * 64; ldc = NTOT;
    }
    for (int k0 = 0; k0 < 64; k0 += 16) {
        {
            int kl = tid & 15, ml = tid >> 4;
#pragma unroll
            for (int p = 0; p < 4; p++)
                As[kl][ml + p * 16] = Aop[(size_t)(ml + p * 16) * lda + (k0 + kl)];
        }
        if (!tb) {
            int nl = tid & 63, kl = tid >> 6;
#pragma unroll
            for (int p = 0; p < 4; p++)
                Bs[kl + p * 4][nl] = Bop[(size_t)(k0 + kl + p * 4) * ldb + nl];
        } else {
            int kl = tid & 15, nl = tid >> 4;
#pragma unroll
            for (int p = 0; p < 4; p++)
                Bs[kl][nl + p * 16] = Bop[(size_t)(nl + p * 16) * ldb + (k0 + kl)];
        }
        __syncthreads();
#pragma unroll
        for (int kk = 0; kk < 16; kk++) {
            float4 av = *(const float4*)&As[kk][ty * 4];
            float4 bv = *(const float4*)&Bs[kk][tx * 4];
            float a_[4] = {av.x, av.y, av.z, av.w};
            float b_[4] = {bv.x, bv.y, bv.z, bv.w};
#pragma unroll
            for (int i = 0; i < 4; i++)
#pragma unroll
                for (int j = 0; j < 4; j++) acc[i][j] += a_[i] * b_[j];
        }
        __syncthreads();
    }
#pragma unroll
    for (int i = 0; i < 4; i++)
#pragma unroll
        for (int j = 0; j < 4; j++)
            Cop[(size_t)(ty * 4 + i) * ldc + (tx * 4 + j)] = acc[i][j];
}

// =====================================================================
// combo2 (per kb): one launch does
//   job A (bx < tilesA, lower only): A_trail -= panel * panel^T
//   job B (bx >= tilesA):            B[kb+1:] -= panel * B_kb
// 128x128 tiles, 8x8 micro. K = 64. alpha=-1, beta=1.
// =====================================================================
__global__ __launch_bounds__(256, 2)
void k_combo2(int kb, int rem)
{
    int c = blockIdx.z;
    int tilesA = (rem + 127) >> 7;
    int bx = blockIdx.x, mb = blockIdx.y;
    bool jobA = bx < tilesA;
    if (jobA && bx > mb) return;
    const float* panel = g_A + (size_t)c * NP * NP + (size_t)(kb + 1) * 64 * NP + (size_t)kb * 64;
    const float* Aop = panel;
    const int lda = NP;
    const int M = rem;
    const float* Bop; int ldb; bool tb; float* Cop; int ldc; int N; int col0;
    if (jobA) {
        Bop = panel; ldb = NP; tb = true;
        Cop = g_A + (size_t)c * NP * NP + (size_t)(kb + 1) * 64 * NP + (size_t)(kb + 1) * 64;
        ldc = NP; N = rem; col0 = bx * 128;
    } else {
        Bop = g_B + (size_t)c * NP * NTOT + (size_t)kb * 64 * NTOT;
        ldb = NTOT; tb = false;
        Cop = g_B + (size_t)c * NP * NTOT + (size_t)(kb + 1) * 64 * NTOT;
        ldc = NTOT; N = NTOT; col0 = (bx - tilesA) * 128;
    }
    const int row0 = mb * 128;
    __shared__ float As[16][132];
    __shared__ float Bs[16][132];
    int tid = threadIdx.x, tx = tid & 15, ty = tid >> 4;
    float acc[8][8];
#pragma unroll
    for (int i = 0; i < 8; i++)
#pragma unroll
        for (int j = 0; j < 8; j++) acc[i][j] = 0.0f;

    for (int k0 = 0; k0 < 64; k0 += 16) {
        // A load (TA=0): As[k][m]
        {
            int rr = tid >> 2, c4 = (tid & 3) << 2;
#pragma unroll
            for (int h = 0; h < 2; h++) {
                int m = row0 + rr + h * 64;
                if (m >= M) m = M - 1;
                float4 v = *(const float4*)(Aop + (size_t)m * lda + k0 + c4);
                As[c4 + 0][rr + h * 64] = v.x;
                As[c4 + 1][rr + h * 64] = v.y;
                As[c4 + 2][rr + h * 64] = v.z;
                As[c4 + 3][rr + h * 64] = v.w;
            }
        }
        if (!tb) {
            int kk = tid >> 4, n8 = (tid & 15) << 3;
#pragma unroll
            for (int h = 0; h < 2; h++) {
                int n = col0 + n8 + h * 4;
                float4 v = *(const float4*)(Bop + (size_t)(k0 + kk) * ldb + n);
                *(float4*)&Bs[kk][n8 + h * 4] = v;
            }
        } else {
            int rr = tid >> 2, c4 = (tid & 3) << 2;
#pragma unroll
            for (int h = 0; h < 2; h++) {
                int n = col0 + rr + h * 64;
                if (n >= N) n = N - 1;
                float4 v = *(const float4*)(Bop + (size_t)n * ldb + k0 + c4);
                Bs[c4 + 0][rr + h * 64] = v.x;
                Bs[c4 + 1][rr + h * 64] = v.y;
                Bs[c4 + 2][rr + h * 64] = v.z;
                Bs[c4 + 3][rr + h * 64] = v.w;
            }
        }
        __syncthreads();
#pragma unroll
        for (int kk = 0; kk < 16; kk++) {
            float4 a0 = *(const float4*)&As[kk][ty * 8];
            float4 a1 = *(const float4*)&As[kk][ty * 8 + 4];
            float4 b0 = *(const float4*)&Bs[kk][tx * 8];
            float4 b1 = *(const float4*)&Bs[kk][tx * 8 + 4];
            float av[8] = {a0.x, a0.y, a0.z, a0.w, a1.x, a1.y, a1.z, a1.w};
            float bv[8] = {b0.x, b0.y, b0.z, b0.w, b1.x, b1.y, b1.z, b1.w};
#pragma unroll
            for (int i = 0; i < 8; i++)
#pragma unroll
                for (int j = 0; j < 8; j++) acc[i][j] += av[i] * bv[j];
        }
        __syncthreads();
    }
#pragma unroll
    for (int i = 0; i < 8; i++) {
        int m = row0 + ty * 8 + i;
        if (m >= M) continue;
#pragma unroll
        for (int j = 0; j < 8; j += 4) {
            int n = col0 + tx * 8 + j;
            if (n >= N) continue;
            float* p = Cop + (size_t)m * ldc + n;
            float4 o = *(const float4*)p;
            o.x -= acc[i][j + 0];
            o.y -= acc[i][j + 1];
            o.z -= acc[i][j + 2];
            o.w -= acc[i][j + 3];
            *(float4*)p = o;
        }
    }
}

// =====================================================================
// H GEMM: H_c = P_c^T * P_c (lower tiles + last col tile), 128x128/8x8
// =====================================================================
__global__ __launch_bounds__(256, 2)
void k_hgemm()
{
    int nb = blockIdx.x, mb = blockIdx.y;
    if (nb > mb && nb != (int)gridDim.x - 1) return;
    int c = blockIdx.z;
    const float* P = g_B + (size_t)c * NP * NTOT;
    float* H = g_H + (size_t)c * NP * NTOT;
    const int row0 = mb * 128, col0 = nb * 128;
    __shared__ float As[16][132];
    __shared__ float Bs[16][132];
    int tid = threadIdx.x, tx = tid & 15, ty = tid >> 4;
    float acc[8][8];
#pragma unroll
    for (int i = 0; i < 8; i++)
#pragma unroll
        for (int j = 0; j < 8; j++) acc[i][j] = 0.0f;

    for (int k0 = 0; k0 < NP; k0 += 16) {
        // A^T load: As[k][m] = P[k0+k][row0+m]
        {
            int kk = tid >> 4, m8 = (tid & 15) << 3;
#pragma unroll
            for (int h = 0; h < 2; h++) {
                float4 v = *(const float4*)(P + (size_t)(k0 + kk) * NTOT + row0 + m8 + h * 4);
                *(float4*)&As[kk][m8 + h * 4] = v;
            }
        }
        {
            int kk = tid >> 4, n8 = (tid & 15) << 3;
#pragma unroll
            for (int h = 0; h < 2; h++) {
                float4 v = *(const float4*)(P + (size_t)(k0 + kk) * NTOT + col0 + n8 + h * 4);
                *(float4*)&Bs[kk][n8 + h * 4] = v;
            }
        }
        __syncthreads();
#pragma unroll
        for (int kk = 0; kk < 16; kk++) {
            float4 a0 = *(const float4*)&As[kk][ty * 8];
            float4 a1 = *(const float4*)&As[kk][ty * 8 + 4];
            float4 b0 = *(const float4*)&Bs[kk][tx * 8];
            float4 b1 = *(const float4*)&Bs[kk][tx * 8 + 4];
            float av[8] = {a0.x, a0.y, a0.z, a0.w, a1.x, a1.y, a1.z, a1.w};
            float bv[8] = {b0.x, b0.y, b0.z, b0.w, b1.x, b1.y, b1.z, b1.w};
#pragma unroll
            for (int i = 0; i < 8; i++)
#pragma unroll
                for (int j = 0; j < 8; j++) acc[i][j] += av[i] * bv[j];
        }
        __syncthreads();
    }
#pragma unroll
    for (int i = 0; i < 8; i++) {
        int m = row0 + ty * 8 + i;
#pragma unroll
        for (int j = 0; j < 8; j += 4) {
            int n = col0 + tx * 8 + j;
            float4 v;
            v.x = acc[i][j + 0];
            v.y = acc[i][j + 1];
            v.z = acc[i][j + 2];
            v.w = acc[i][j + 3];
            *(float4*)(H + (size_t)m * NTOT + n) = v;
        }
    }
}

// =====================================================================
// Symmetrize H: copy lower triangle -> upper (cols < 1024 only)
// =====================================================================
__global__ void k_symH()
{
    int tc = blockIdx.x, tr = blockIdx.y;
    if (tc < tr) return;
    int c = blockIdx.z;
    float* H = g_H + (size_t)c * NP * NTOT;
    __shared__ float s[32][33];
    int x = threadIdx.x, y0 = threadIdx.y;
    for (int yy = y0; yy < 32; yy += 8)
        s[yy][x] = H[(size_t)(tc * 32 + yy) * NTOT + tr * 32 + x];
    __syncthreads();
    for (int yy = y0; yy < 32; yy += 8) {
        int i = tr * 32 + yy, j = tc * 32 + x;
        if (j > i) H[(size_t)i * NTOT + j] = s[x][yy];
    }
}

// =====================================================================
// Final outputs
// =====================================================================
__global__ void k_fmean(float* __restrict__ out)
{
    int idx = blockIdx.x * blockDim.x + threadIdx.x;
    if (idx >= 4096) return;
    int b = idx >> 10, j = idx & 1023;
    float v = 0.0f;
#pragma unroll
    for (int c = 0; c < LT; c++)
        v += g_M[c * LT + b] * g_H[(size_t)c * NP * NTOT + (size_t)j * NTOT + 1024];
    out[OFF_FMEAN + idx] = v;
    out[OFF_OUT4 + (size_t)j * LT + b] = v;
}

__global__ void k_output(float* __restrict__ out)
{
    size_t t = (size_t)blockIdx.x * blockDim.x + threadIdx.x;
    if (t >= (size_t)4096 * 1024) return;
    int g = (int)(t & 1023);
    size_t ig = t >> 10;
    int a = (int)(ig >> 10);
    int i = (int)(ig & 1023);
    int b = g >> 8;
    int j0 = (g & 255) << 2;
    float4 cxx = *(const float4*)&g_Cxx[(size_t)i * NP + j0];
    float Tab = g_Tm[a * LT + b];
    float4 acc;
    acc.x = Tab * cxx.x;
    acc.y = Tab * cxx.y;
    acc.z = Tab * cxx.z;
    acc.w = Tab * cxx.w;
#pragma unroll
    for (int c = 0; c < LT; c++) {
        float mm = g_M[c * LT + a] * g_M[c * LT + b];
        float4 h = *(const float4*)&g_H[(size_t)c * NP * NTOT + (size_t)i * NTOT + j0];
        acc.x -= mm * h.x;
        acc.y -= mm * h.y;
        acc.z -= mm * h.z;
        acc.w -= mm * h.w;
    }
    size_t col0 = (size_t)b * 1024 + j0;
    *(float4*)&out[OFF_FVAR + ig * 4096 + col0] = acc;
    float4 nz = make_float4(0.f, 0.f, 0.f, 0.f);
    if (ig >= col0 && ig < col0 + 4) {
        float nv = g_noise[a];
        int jj = (int)(ig - col0);
        if (jj == 0) nz.x = nv;
        else if (jj == 1) nz.y = nv;
        else if (jj == 2) nz.z = nv;
        else nz.w = nv;
    }
    *(float4*)&out[OFF_NOISE + ig * 4096 + col0] = nz;
}

// =====================================================================
// Host side
// =====================================================================
extern "C" void kernel_launch(void* const* d_in, const int* in_sizes, int n_in,
                              void* d_out, int out_size)
{
    const float* X        = (const float*)d_in[0];
    const float* test_X   = (const float*)d_in[1];
    const float* Y        = (const float*)d_in[2];
    const float* lnoise   = (const float*)d_in[3];
    const float* cfac     = (const float*)d_in[4];
    const float* lvar     = (const float*)d_in[5];
    const float* lls      = (const float*)d_in[6];
    int rank = in_sizes[4] / LT;
    float* out = (float*)d_out;

    k_setup<<<1, 32>>>(cfac, lvar, lnoise, rank);
    dim3 rg(64, 64);
    k_rbf<<<rg, 256>>>(X, X, lls, 2);           // A_c = lambda_c*C + I
    k_rbf<<<rg, 256>>>(X, test_X, lls, 1);      // Cx into B_c
    k_rbf<<<rg, 256>>>(test_X, test_X, lls, 0); // Cxx
    k_y<<<(NP + 255) / 256, 256>>>(Y);

    // ---- batched blocked Cholesky fused with forward solve ----
    for (int kb = 0; kb < NKB; kb++) {
        int rem = NP - 64 * (kb + 1);
        k_potf2<<<dim3(1, 1, LT), 256>>>(kb);
        // panel TRSM + B diag solve in one launch
        k_combo1<<<dim3((rem >> 6) + (NTOT >> 6), 1, LT), 256>>>(kb, rem);
        if (rem > 0) {
            int tilesA = (rem + 127) >> 7;
            // trailing SYRK update + B off-diag update in one launch
            k_combo2<<<dim3(tilesA + (NTOT >> 7), tilesA, LT), 256>>>(kb, rem);
        }
    }

    // ---- H_c = P_c^T * P_c (lower + last col tile), then symmetrize ----
    k_hgemm<<<dim3(NTOT / 128, NP / 128, LT), 256>>>();
    k_symH<<<dim3(32, 32, LT), dim3(32, 8)>>>();

    // ---- outputs ----
    k_fmean<<<16, 256>>>(out);
    k_output<<<16384, 256>>>(out);
}

// round 5
// speedup vs baseline: 1.6290x; 1.0336x over previous
#include <cuda_runtime.h>
#include <math.h>

// Problem constants (fixed instance)
constexpr int NP   = 1024;   // N == N_ (train/test points)
constexpr int LT   = 4;      // tasks
constexpr int RNK_MAX = 8;
constexpr int NTOT = 1152;   // RHS width: 1024 Cx cols + 1 ytilde col + pad to 9*128
constexpr int NKB  = 16;     // 1024 / 64 block steps

// Output offsets (fp32 elements)
constexpr size_t OFF_FMEAN = 0;
constexpr size_t OFF_FVAR  = 4096;
constexpr size_t OFF_NOISE = OFF_FVAR + (size_t)4096 * 4096;
constexpr size_t OFF_OUT4  = OFF_NOISE + (size_t)4096 * 4096;

// -------- device scratch (static, no allocation) --------
__device__ float g_A[LT * NP * NP];          // lambda_c*C + I, then Cholesky L (lower)
__device__ float g_B[LT * NP * NTOT];        // RHS -> forward-solved P_c (and w_c in col 1024)
__device__ float g_H[LT * NP * NTOT];        // H_c = P_c^T * P_c  (col 1024 = g_c)
__device__ float g_Cxx[NP * NP];             // rbf(test_X, test_X)
__device__ float g_Linv[LT * NKB * 64 * 64]; // per-step 64x64 diag-block inverses
__device__ float g_lambda[LT];
__device__ float g_R[LT * LT];               // R = U^T Dn^{-1/2}
__device__ float g_M[LT * LT];               // M = R * T
__device__ float g_Tm[LT * LT];              // task_K
__device__ float g_noise[LT];                // exp(log_noise)

// =====================================================================
// Small setup: task_K, 4x4 Jacobi eigendecomposition, R, M (fp64)
// =====================================================================
__global__ void k_setup(const float* __restrict__ cf,
                        const float* __restrict__ log_var,
                        const float* __restrict__ log_noise,
                        int rank)
{
    if (threadIdx.x != 0) return;
    double T[LT][LT], Tt[LT][LT], U[LT][LT], sv[LT];
    for (int a = 0; a < LT; a++) sv[a] = exp(-0.5 * (double)log_noise[a]);
    for (int a = 0; a < LT; a++)
        for (int b = 0; b < LT; b++) {
            double s = 0.0;
            for (int r = 0; r < rank && r < RNK_MAX; r++)
                s += (double)cf[a * rank + r] * (double)cf[b * rank + r];
            if (a == b) s += exp((double)log_var[a]);
            T[a][b] = s;
        }
    for (int a = 0; a < LT; a++)
        for (int b = 0; b < LT; b++) {
            Tt[a][b] = sv[a] * sv[b] * T[a][b];
            U[a][b] = (a == b) ? 1.0 : 0.0;
        }
    for (int sweep = 0; sweep < 60; sweep++) {
        double off = 0.0;
        for (int p = 0; p < LT; p++)
            for (int q = p + 1; q < LT; q++) off += Tt[p][q] * Tt[p][q];
        if (off < 1e-28) break;
        for (int p = 0; p < LT; p++)
            for (int q = p + 1; q < LT; q++) {
                double apq = Tt[p][q];
                if (fabs(apq) < 1e-300) continue;
                double tau = (Tt[q][q] - Tt[p][p]) / (2.0 * apq);
                double tt = ((tau >= 0.0) ? 1.0 : -1.0) / (fabs(tau) + sqrt(1.0 + tau * tau));
                double cc = 1.0 / sqrt(1.0 + tt * tt);
                double ss = tt * cc;
                for (int k = 0; k < LT; k++) {
                    double akp = Tt[k][p], akq = Tt[k][q];
                    Tt[k][p] = cc * akp - ss * akq;
                    Tt[k][q] = ss * akp + cc * akq;
                }
                for (int k = 0; k < LT; k++) {
                    double apk = Tt[p][k], aqk = Tt[q][k];
                    Tt[p][k] = cc * apk - ss * aqk;
                    Tt[q][k] = ss * apk + cc * aqk;
                }
                for (int k = 0; k < LT; k++) {
                    double ukp = U[k][p], ukq = U[k][q];
                    U[k][p] = cc * ukp - ss * ukq;
                    U[k][q] = ss * ukp + cc * ukq;
                }
            }
    }
    double R[LT][LT];
    for (int c = 0; c < LT; c++) {
        g_lambda[c] = (float)Tt[c][c];
        for (int a = 0; a < LT; a++) {
            R[c][a] = U[a][c] * sv[a];
            g_R[c * LT + a] = (float)R[c][a];
        }
    }
    for (int c = 0; c < LT; c++)
        for (int b = 0; b < LT; b++) {
            double m = 0.0;
            for (int a = 0; a < LT; a++) m += R[c][a] * T[a][b];
            g_M[c * LT + b] = (float)m;
        }
    for (int a = 0; a < LT; a++) {
        for (int b = 0; b < LT; b++) g_Tm[a * LT + b] = (float)T[a][b];
        g_noise[a] = (float)exp((double)log_noise[a]);
    }
}

// =====================================================================
// RBF kernels. mode 0: Cxx ; mode 1: Cx into B ; mode 2: A_c
// =====================================================================
__global__ void k_rbf(const float* __restrict__ X1, const float* __restrict__ X2,
                      const float* __restrict__ log_ls, int mode)
{
    __shared__ float xs1[16][8];
    __shared__ float xs2[16][8];
    int tid = threadIdx.x;
    int bx = blockIdx.x, by = blockIdx.y;
    if (tid < 128) {
        xs1[tid >> 3][tid & 7] = X1[(by * 16 + (tid >> 3)) * 8 + (tid & 7)];
    } else {
        int q = tid - 128;
        xs2[q >> 3][q & 7] = X2[(bx * 16 + (q >> 3)) * 8 + (q & 7)];
    }
    __syncthreads();
    int tx = tid & 15, ty = tid >> 4;
    float inv_ls2 = expf(-2.0f * log_ls[0]);
    float d2 = 0.0f;
#pragma unroll
    for (int d = 0; d < 8; d++) {
        float df = xs1[ty][d] - xs2[tx][d];
        d2 += df * df;
    }
    float kv = expf(-0.5f * d2 * inv_ls2);
    int i = by * 16 + ty, j = bx * 16 + tx;
    if (mode == 0) {
        g_Cxx[(size_t)i * NP + j] = kv;
    } else if (mode == 1) {
#pragma unroll
        for (int c = 0; c < LT; c++)
            g_B[(size_t)c * NP * NTOT + (size_t)i * NTOT + j] = kv;
    } else {
        float dg = (i == j) ? 1.0f : 0.0f;
#pragma unroll
        for (int c = 0; c < LT; c++)
            g_A[(size_t)c * NP * NP + (size_t)i * NP + j] = g_lambda[c] * kv + dg;
    }
}

// ytilde into column 1024 of each B_c, zero the pad columns
__global__ void k_y(const float* __restrict__ Y)
{
    int i = blockIdx.x * blockDim.x + threadIdx.x;
    if (i >= NP) return;
    float y[LT];
#pragma unroll
    for (int a = 0; a < LT; a++) y[a] = Y[i * LT + a];
#pragma unroll
    for (int c = 0; c < LT; c++) {
        float v = 0.0f;
#pragma unroll
        for (int a = 0; a < LT; a++) v += g_R[c * LT + a] * y[a];
        size_t base = (size_t)c * NP * NTOT + (size_t)i * NTOT;
        g_B[base + 1024] = v;
        for (int p = 1025; p < NTOT; p++) g_B[base + p] = 0.0f;
    }
}

// =====================================================================
// potf2 (kb=0 only): factor 64x64 diag block + produce L^{-1}
// =====================================================================
__global__ void k_potf2(int kb)
{
    int c = blockIdx.z;
    float* Ad = g_A + (size_t)c * NP * NP + (size_t)kb * 64 * NP + (size_t)kb * 64;
    float* Li = g_Linv + ((size_t)c * NKB + kb) * 64 * 64;
    __shared__ float s[64][65];
    __shared__ float vi[64][65];
    __shared__ float sdiag[64];
    int tid = threadIdx.x;
    int r = tid & 63, q = tid >> 6;
    for (int p = tid; p < 64 * 64; p += 256) {
        int rr = p >> 6, qq = p & 63;
        s[rr][qq] = Ad[(size_t)rr * NP + qq];
        vi[rr][qq] = (rr == qq) ? 1.0f : 0.0f;
    }
    __syncthreads();
#pragma unroll 1
    for (int j = 0; j < 64; j++) {
        float d = rsqrtf(s[j][j]);
        if (q == 0 && r > j)  s[r][j] *= d;
        if (q == 1 && r <= j) vi[j][r] *= d;
        if (q == 2 && r == j) sdiag[j] = s[j][j] * d;
        __syncthreads();
        if (r > j) {
            float sij = s[r][j];
            for (int t = j + 1 + q; t < 64; t += 4)
                s[r][t] -= sij * s[t][j];
            for (int t = q; t <= j; t += 4)
                vi[r][t] -= sij * vi[j][t];
        }
        __syncthreads();
    }
    for (int p = tid; p < 64 * 64; p += 256) {
        int rr = p >> 6, qq = p & 63;
        if (qq < rr) Ad[(size_t)rr * NP + qq] = s[rr][qq];
        else if (qq == rr) Ad[(size_t)rr * NP + qq] = sdiag[rr];
        Li[p] = vi[rr][qq];
    }
}

// =====================================================================
// combo1 (per kb): panel TRSM tiles + B diag-block solve, one launch
// =====================================================================
__global__ void k_combo1(int kb, int rem)
{
    int c = blockIdx.z;
    const float* Li = g_Linv + ((size_t)c * NKB + kb) * 4096;
    int panelTiles = rem >> 6;
    int bx = blockIdx.x;
    __shared__ float As[16][68];
    __shared__ float Bs[16][68];
    int tid = threadIdx.x, tx = tid & 15, ty = tid >> 4;
    float acc[4][4];
#pragma unroll
    for (int i = 0; i < 4; i++)
#pragma unroll
        for (int j = 0; j < 4; j++) acc[i][j] = 0.0f;

    const float* Aop; const float* Bop; float* Cop;
    int lda, ldb, ldc; bool tb;
    if (bx < panelTiles) {
        float* panel = g_A + (size_t)c * NP * NP + (size_t)(kb + 1) * 64 * NP + (size_t)kb * 64;
        Aop = panel + (size_t)bx * 64 * NP; lda = NP;
        Bop = Li; ldb = 64; tb = true;
        Cop = panel + (size_t)bx * 64 * NP; ldc = NP;
    } else {
        int nb = bx - panelTiles;
        float* Bk = g_B + (size_t)c * NP * NTOT + (size_t)kb * 64 * NTOT;
        Aop = Li; lda = 64; tb = false;
        Bop = Bk + nb * 64; ldb = NTOT;
        Cop = Bk + nb * 64; ldc = NTOT;
    }
    for (int k0 = 0; k0 < 64; k0 += 16) {
        {
            int kl = tid & 15, ml = tid >> 4;
#pragma unroll
            for (int p = 0; p < 4; p++)
                As[kl][ml + p * 16] = Aop[(size_t)(ml + p * 16) * lda + (k0 + kl)];
        }
        if (!tb) {
            int nl = tid & 63, kl = tid >> 6;
#pragma unroll
            for (int p = 0; p < 4; p++)
                Bs[kl + p * 4][nl] = Bop[(size_t)(k0 + kl + p * 4) * ldb + nl];
        } else {
            int kl = tid & 15, nl = tid >> 4;
#pragma unroll
            for (int p = 0; p < 4; p++)
                Bs[kl][nl + p * 16] = Bop[(size_t)(nl + p * 16) * ldb + (k0 + kl)];
        }
        __syncthreads();
#pragma unroll
        for (int kk = 0; kk < 16; kk++) {
            float4 av = *(const float4*)&As[kk][ty * 4];
            float4 bv = *(const float4*)&Bs[kk][tx * 4];
            float a_[4] = {av.x, av.y, av.z, av.w};
            float b_[4] = {bv.x, bv.y, bv.z, bv.w};
#pragma unroll
            for (int i = 0; i < 4; i++)
#pragma unroll
                for (int j = 0; j < 4; j++) acc[i][j] += a_[i] * b_[j];
        }
        __syncthreads();
    }
#pragma unroll
    for (int i = 0; i < 4; i++)
#pragma unroll
        for (int j = 0; j < 4; j++)
            Cop[(size_t)(ty * 4 + i) * ldc + (tx * 4 + j)] = acc[i][j];
}

// =====================================================================
// combo2 (per kb): one launch does
//   job A (bx < tilesA, lower only): A_trail -= panel * panel^T
//   job B (bx >= tilesA):            B[kb+1:] -= panel * B_kb
// CTA (0,0,jobA) additionally factors the next 64x64 diag block
// (fused potf2(kb+1)) and writes L + Linv, reusing its smem pool.
// =====================================================================
__global__ __launch_bounds__(256, 2)
void k_combo2(int kb, int rem)
{
    __shared__ float pool[8448];
    float* Asb = pool;          // [16][132]
    float* Bsb = pool + 2112;   // [16][132]
    int c = blockIdx.z;
    int tilesA = (rem + 127) >> 7;
    int bx = blockIdx.x, mb = blockIdx.y;
    bool jobA = bx < tilesA;
    if (jobA && bx > mb) return;
    const float* panel = g_A + (size_t)c * NP * NP + (size_t)(kb + 1) * 64 * NP + (size_t)kb * 64;
    const float* Aop = panel;
    const int lda = NP;
    const int M = rem;
    const float* Bop; int ldb; bool tb; float* Cop; int ldc; int N; int col0;
    if (jobA) {
        Bop = panel; ldb = NP; tb = true;
        Cop = g_A + (size_t)c * NP * NP + (size_t)(kb + 1) * 64 * NP + (size_t)(kb + 1) * 64;
        ldc = NP; N = rem; col0 = bx * 128;
    } else {
        Bop = g_B + (size_t)c * NP * NTOT + (size_t)kb * 64 * NTOT;
        ldb = NTOT; tb = false;
        Cop = g_B + (size_t)c * NP * NTOT + (size_t)(kb + 1) * 64 * NTOT;
        ldc = NTOT; N = NTOT; col0 = (bx - tilesA) * 128;
    }
    const int row0 = mb * 128;
    int tid = threadIdx.x, tx = tid & 15, ty = tid >> 4;
    float acc[8][8];
#pragma unroll
    for (int i = 0; i < 8; i++)
#pragma unroll
        for (int j = 0; j < 8; j++) acc[i][j] = 0.0f;

    for (int k0 = 0; k0 < 64; k0 += 16) {
        {
            int rr = tid >> 2, c4 = (tid & 3) << 2;
#pragma unroll
            for (int h = 0; h < 2; h++) {
                int m = row0 + rr + h * 64;
                if (m >= M) m = M - 1;
                float4 v = *(const float4*)(Aop + (size_t)m * lda + k0 + c4);
                Asb[(c4 + 0) * 132 + rr + h * 64] = v.x;
                Asb[(c4 + 1) * 132 + rr + h * 64] = v.y;
                Asb[(c4 + 2) * 132 + rr + h * 64] = v.z;
                Asb[(c4 + 3) * 132 + rr + h * 64] = v.w;
            }
        }
        if (!tb) {
            int kk = tid >> 4, n8 = (tid & 15) << 3;
#pragma unroll
            for (int h = 0; h < 2; h++) {
                int n = col0 + n8 + h * 4;
                float4 v = *(const float4*)(Bop + (size_t)(k0 + kk) * ldb + n);
                *(float4*)&Bsb[kk * 132 + n8 + h * 4] = v;
            }
        } else {
            int rr = tid >> 2, c4 = (tid & 3) << 2;
#pragma unroll
            for (int h = 0; h < 2; h++) {
                int n = col0 + rr + h * 64;
                if (n >= N) n = N - 1;
                float4 v = *(const float4*)(Bop + (size_t)n * ldb + k0 + c4);
                Bsb[(c4 + 0) * 132 + rr + h * 64] = v.x;
                Bsb[(c4 + 1) * 132 + rr + h * 64] = v.y;
                Bsb[(c4 + 2) * 132 + rr + h * 64] = v.z;
                Bsb[(c4 + 3) * 132 + rr + h * 64] = v.w;
            }
        }
        __syncthreads();
#pragma unroll
        for (int kk = 0; kk < 16; kk++) {
            float4 a0 = *(const float4*)&Asb[kk * 132 + ty * 8];
            float4 a1 = *(const float4*)&Asb[kk * 132 + ty * 8 + 4];
            float4 b0 = *(const float4*)&Bsb[kk * 132 + tx * 8];
            float4 b1 = *(const float4*)&Bsb[kk * 132 + tx * 8 + 4];
            float av[8] = {a0.x, a0.y, a0.z, a0.w, a1.x, a1.y, a1.z, a1.w};
            float bv[8] = {b0.x, b0.y, b0.z, b0.w, b1.x, b1.y, b1.z, b1.w};
#pragma unroll
            for (int i = 0; i < 8; i++)
#pragma unroll
                for (int j = 0; j < 8; j++) acc[i][j] += av[i] * bv[j];
        }
        __syncthreads();
    }

    bool fuse = jobA && bx == 0 && mb == 0 && (kb + 1 < NKB);

#pragma unroll
    for (int i = 0; i < 8; i++) {
        int m = row0 + ty * 8 + i;
        if (m >= M) continue;
#pragma unroll
        for (int j = 0; j < 8; j += 4) {
            int n = col0 + tx * 8 + j;
            if (n >= N) continue;
            float* p = Cop + (size_t)m * ldc + n;
            float4 o = *(const float4*)p;
            o.x -= acc[i][j + 0];
            o.y -= acc[i][j + 1];
            o.z -= acc[i][j + 2];
            o.w -= acc[i][j + 3];
            *(float4*)p = o;
            if (fuse && m < 64 && n < 64) {
                // capture next diag block into smem pool (s, stride 65)
                pool[m * 65 + n + 0] = o.x;
                pool[m * 65 + n + 1] = o.y;
                pool[m * 65 + n + 2] = o.z;
                pool[m * 65 + n + 3] = o.w;
            }
        }
    }

    if (fuse) {
        // ---- fused potf2(kb+1): factor + invert 64x64 from pool ----
        float* s  = pool;          // [64][65]
        float* vi = pool + 4224;   // [64][65]
        float* sd = pool + 8384;   // [64]
        int r = tid & 63, q = tid >> 6;
        for (int p = tid; p < 64 * 64; p += 256)
            vi[(p >> 6) * 65 + (p & 63)] = ((p >> 6) == (p & 63)) ? 1.0f : 0.0f;
        __syncthreads();
#pragma unroll 1
        for (int j = 0; j < 64; j++) {
            float d = rsqrtf(s[j * 65 + j]);
            if (q == 0 && r > j)  s[r * 65 + j] *= d;
            if (q == 1 && r <= j) vi[j * 65 + r] *= d;
            if (q == 2 && r == j) sd[j] = s[j * 65 + j] * d;
            __syncthreads();
            if (r > j) {
                float sij = s[r * 65 + j];
                for (int t = j + 1 + q; t < 64; t += 4)
                    s[r * 65 + t] -= sij * s[t * 65 + j];
                for (int t = q; t <= j; t += 4)
                    vi[r * 65 + t] -= sij * vi[j * 65 + t];
            }
            __syncthreads();
        }
        int kbn = kb + 1;
        float* Ad = g_A + (size_t)c * NP * NP + (size_t)kbn * 64 * NP + (size_t)kbn * 64;
        float* Li = g_Linv + ((size_t)c * NKB + kbn) * 4096;
        for (int p = tid; p < 64 * 64; p += 256) {
            int rr = p >> 6, qq = p & 63;
            if (qq < rr) Ad[(size_t)rr * NP + qq] = s[rr * 65 + qq];
            else if (qq == rr) Ad[(size_t)rr * NP + qq] = sd[rr];
            Li[p] = vi[rr * 65 + qq];
        }
    }
}

// =====================================================================
// H GEMM: H_c = P_c^T * P_c (lower tiles + last col tile)
// 128x128/8x8, double-buffered smem, register-staged LDG pipeline.
// =====================================================================
__global__ __launch_bounds__(256, 2)
void k_hgemm()
{
    int nb = blockIdx.x, mb = blockIdx.y;
    if (nb > mb && nb != (int)gridDim.x - 1) return;
    int c = blockIdx.z;
    const float* P = g_B + (size_t)c * NP * NTOT;
    float* H = g_H + (size_t)c * NP * NTOT;
    const int row0 = mb * 128, col0 = nb * 128;
    __shared__ float As[2][16][132];
    __shared__ float Bs[2][16][132];
    int tid = threadIdx.x, tx = tid & 15, ty = tid >> 4;
    int kk = tid >> 4, m8 = (tid & 15) << 3;
    float acc[8][8];
#pragma unroll
    for (int i = 0; i < 8; i++)
#pragma unroll
        for (int j = 0; j < 8; j++) acc[i][j] = 0.0f;

    float4 ra0, ra1, rb0, rb1;
    {
        const float* Pk = P + (size_t)kk * NTOT;
        ra0 = *(const float4*)(Pk + row0 + m8);
        ra1 = *(const float4*)(Pk + row0 + m8 + 4);
        rb0 = *(const float4*)(Pk + col0 + m8);
        rb1 = *(const float4*)(Pk + col0 + m8 + 4);
    }
    *(float4*)&As[0][kk][m8]     = ra0;
    *(float4*)&As[0][kk][m8 + 4] = ra1;
    *(float4*)&Bs[0][kk][m8]     = rb0;
    *(float4*)&Bs[0][kk][m8 + 4] = rb1;
    __syncthreads();
    int buf = 0;
#pragma unroll 1
    for (int t = 0; t < 64; t++) {
        if (t < 63) {
            const float* Pk = P + (size_t)((t + 1) * 16 + kk) * NTOT;
            ra0 = *(const float4*)(Pk + row0 + m8);
            ra1 = *(const float4*)(Pk + row0 + m8 + 4);
            rb0 = *(const float4*)(Pk + col0 + m8);
            rb1 = *(const float4*)(Pk + col0 + m8 + 4);
        }
#pragma unroll
        for (int k2 = 0; k2 < 16; k2++) {
            float4 a0 = *(const float4*)&As[buf][k2][ty * 8];
            float4 a1 = *(const float4*)&As[buf][k2][ty * 8 + 4];
            float4 b0 = *(const float4*)&Bs[buf][k2][tx * 8];
            float4 b1 = *(const float4*)&Bs[buf][k2][tx * 8 + 4];
            float av[8] = {a0.x, a0.y, a0.z, a0.w, a1.x, a1.y, a1.z, a1.w};
            float bv[8] = {b0.x, b0.y, b0.z, b0.w, b1.x, b1.y, b1.z, b1.w};
#pragma unroll
            for (int i = 0; i < 8; i++)
#pragma unroll
                for (int j = 0; j < 8; j++) acc[i][j] += av[i] * bv[j];
        }
        if (t < 63) {
            *(float4*)&As[buf ^ 1][kk][m8]     = ra0;
            *(float4*)&As[buf ^ 1][kk][m8 + 4] = ra1;
            *(float4*)&Bs[buf ^ 1][kk][m8]     = rb0;
            *(float4*)&Bs[buf ^ 1][kk][m8 + 4] = rb1;
        }
        __syncthreads();
        buf ^= 1;
    }
#pragma unroll
    for (int i = 0; i < 8; i++) {
        int m = row0 + ty * 8 + i;
#pragma unroll
        for (int j = 0; j < 8; j += 4) {
            int n = col0 + tx * 8 + j;
            float4 v;
            v.x = acc[i][j + 0];
            v.y = acc[i][j + 1];
            v.z = acc[i][j + 2];
            v.w = acc[i][j + 3];
            *(float4*)(H + (size_t)m * NTOT + n) = v;
        }
    }
}

// =====================================================================
// Symmetrize H: copy lower triangle -> upper (cols < 1024 only)
// =====================================================================
__global__ void k_symH()
{
    int tc = blockIdx.x, tr = blockIdx.y;
    if (tc < tr) return;
    int c = blockIdx.z;
    float* H = g_H + (size_t)c * NP * NTOT;
    __shared__ float s[32][33];
    int x = threadIdx.x, y0 = threadIdx.y;
    for (int yy = y0; yy < 32; yy += 8)
        s[yy][x] = H[(size_t)(tc * 32 + yy) * NTOT + tr * 32 + x];
    __syncthreads();
    for (int yy = y0; yy < 32; yy += 8) {
        int i = tr * 32 + yy, j = tc * 32 + x;
        if (j > i) H[(size_t)i * NTOT + j] = s[x][yy];
    }
}

// =====================================================================
// Final outputs
// =====================================================================
__global__ void k_fmean(float* __restrict__ out)
{
    int idx = blockIdx.x * blockDim.x + threadIdx.x;
    if (idx >= 4096) return;
    int b = idx >> 10, j = idx & 1023;
    float v = 0.0f;
#pragma unroll
    for (int c = 0; c < LT; c++)
        v += g_M[c * LT + b] * g_H[(size_t)c * NP * NTOT + (size_t)j * NTOT + 1024];
    out[OFF_FMEAN + idx] = v;
    out[OFF_OUT4 + (size_t)j * LT + b] = v;
}

__global__ void k_output(float* __restrict__ out)
{
    size_t t = (size_t)blockIdx.x * blockDim.x + threadIdx.x;
    if (t >= (size_t)4096 * 1024) return;
    int g = (int)(t & 1023);
    size_t ig = t >> 10;
    int a = (int)(ig >> 10);
    int i = (int)(ig & 1023);
    int b = g >> 8;
    int j0 = (g & 255) << 2;
    float4 cxx = *(const float4*)&g_Cxx[(size_t)i * NP + j0];
    float Tab = g_Tm[a * LT + b];
    float4 acc;
    acc.x = Tab * cxx.x;
    acc.y = Tab * cxx.y;
    acc.z = Tab * cxx.z;
    acc.w = Tab * cxx.w;
#pragma unroll
    for (int c = 0; c < LT; c++) {
        float mm = g_M[c * LT + a] * g_M[c * LT + b];
        float4 h = *(const float4*)&g_H[(size_t)c * NP * NTOT + (size_t)i * NTOT + j0];
        acc.x -= mm * h.x;
        acc.y -= mm * h.y;
        acc.z -= mm * h.z;
        acc.w -= mm * h.w;
    }
    size_t col0 = (size_t)b * 1024 + j0;
    *(float4*)&out[OFF_FVAR + ig * 4096 + col0] = acc;
    float4 nz = make_float4(0.f, 0.f, 0.f, 0.f);
    if (ig >= col0 && ig < col0 + 4) {
        float nv = g_noise[a];
        int jj = (int)(ig - col0);
        if (jj == 0) nz.x = nv;
        else if (jj == 1) nz.y = nv;
        else if (jj == 2) nz.z = nv;
        else nz.w = nv;
    }
    *(float4*)&out[OFF_NOISE + ig * 4096 + col0] = nz;
}

// =====================================================================
// Host side
// =====================================================================
extern "C" void kernel_launch(void* const* d_in, const int* in_sizes, int n_in,
                              void* d_out, int out_size)
{
    const float* X        = (const float*)d_in[0];
    const float* test_X   = (const float*)d_in[1];
    const float* Y        = (const float*)d_in[2];
    const float* lnoise   = (const float*)d_in[3];
    const float* cfac     = (const float*)d_in[4];
    const float* lvar     = (const float*)d_in[5];
    const float* lls      = (const float*)d_in[6];
    int rank = in_sizes[4] / LT;
    float* out = (float*)d_out;

    k_setup<<<1, 32>>>(cfac, lvar, lnoise, rank);
    dim3 rg(64, 64);
    k_rbf<<<rg, 256>>>(X, X, lls, 2);           // A_c = lambda_c*C + I
    k_rbf<<<rg, 256>>>(X, test_X, lls, 1);      // Cx into B_c
    k_rbf<<<rg, 256>>>(test_X, test_X, lls, 0); // Cxx
    k_y<<<(NP + 255) / 256, 256>>>(Y);

    // ---- batched blocked Cholesky fused with forward solve ----
    // potf2(0) standalone; potf2(kb+1) fused into combo2(kb).
    k_potf2<<<dim3(1, 1, LT), 256>>>(0);
    for (int kb = 0; kb < NKB; kb++) {
        int rem = NP - 64 * (kb + 1);
        k_combo1<<<dim3((rem >> 6) + (NTOT >> 6), 1, LT), 256>>>(kb, rem);
        if (rem > 0) {
            int tilesA = (rem + 127) >> 7;
            k_combo2<<<dim3(tilesA + (NTOT >> 7), tilesA, LT), 256>>>(kb, rem);
        }
    }

    // ---- H_c = P_c^T * P_c (lower + last col tile), then symmetrize ----
    k_hgemm<<<dim3(NTOT / 128, NP / 128, LT), 256>>>();
    k_symH<<<dim3(32, 32, LT), dim3(32, 8)>>>();

    // ---- outputs ----
    k_fmean<<<16, 256>>>(out);
    k_output<<<16384, 256>>>(out);
}